// round 1
// baseline (speedup 1.0000x reference)
#include <cuda_runtime.h>

// ---------------------------------------------------------------------------
// MultiheadAttention with low-rank-augmented in/out projections.
// T=1024, B=8, E=1024, H=16, R=16, HD=64.
//
// Pipeline:
//   1) W_eff = W + L@R for in/out projections (rank-16 fold)
//   2) in-proj GEMM (8192x3072x1024), epilogue scatters to Q/K/V (B,H,T,64),
//      q scaled by 1/sqrt(64)=0.125
//   3) fused attention w/ online softmax + rel_pos_bias (per (b,h))
//   4) out-proj GEMM (8192x1024x1024) -> d_out (T,B,E)
// All fp32.
// ---------------------------------------------------------------------------

namespace {
constexpr int Tt = 1024;
constexpr int Bb = 8;
constexpr int Ee = 1024;
constexpr int Hh = 16;
constexpr int Rr = 16;
constexpr int HD = 64;
constexpr int F3 = 3 * Ee;          // 3072
constexpr int Nrows = Tt * Bb;      // 8192
}

// Scratch (device globals; no runtime allocation).
__device__ float g_Weff_in[F3 * Ee];          // 12 MB
__device__ float g_Weff_out[Ee * Ee];         // 4 MB
__device__ float g_Q[Bb * Hh * Tt * HD];      // 32 MB
__device__ float g_K[Bb * Hh * Tt * HD];      // 32 MB
__device__ float g_V[Bb * Hh * Tt * HD];      // 32 MB
__device__ float g_AO[Nrows * Ee];            // 32 MB

// ---------------------------------------------------------------------------
// W_eff[f][e] = W[f][e] + sum_r L[f][r] * R[r][e]
// ---------------------------------------------------------------------------
template <int WHICH>
__global__ void weff_kernel(const float* __restrict__ W,
                            const float* __restrict__ L,
                            const float* __restrict__ Rm)
{
    const int F = (WHICH == 0) ? F3 : Ee;
    float* out = (WHICH == 0) ? g_Weff_in : g_Weff_out;
    int idx = blockIdx.x * 256 + threadIdx.x;
    if (idx >= F * Ee) return;
    int f = idx >> 10;       // / 1024
    int e = idx & 1023;
    float s = W[idx];
#pragma unroll
    for (int r = 0; r < Rr; ++r)
        s = fmaf(L[f * Rr + r], Rm[r * Ee + e], s);
    out[idx] = s;
}

// ---------------------------------------------------------------------------
// Tiled fp32 GEMM: C[m][n] = dot(A[m,:], W[n,:]) + bias[n]
// A: MxK row-major, W: NxK row-major. BM=BN=128, BK=16, 256 thr, 8x8 micro.
// MODE 0: A = query, W = g_Weff_in, scatter to Q/K/V (scale q by 0.125)
// MODE 1: A = g_AO,  W = g_Weff_out, write to `out` row-major MxN
// ---------------------------------------------------------------------------
template <int MODE>
__global__ __launch_bounds__(256)
void gemm128(const float* __restrict__ Ain,
             const float* __restrict__ bias,
             float* __restrict__ out,
             int M, int N, int K)
{
    const float* A = (MODE == 0) ? Ain : g_AO;
    const float* W = (MODE == 0) ? g_Weff_in : g_Weff_out;

    __shared__ float As[16][128];
    __shared__ float Bs[16][128];

    const int m0 = blockIdx.y * 128;
    const int n0 = blockIdx.x * 128;
    const int tid = threadIdx.x;
    const int tx = tid & 15;   // column group
    const int ty = tid >> 4;   // row group

    float acc[8][8];
#pragma unroll
    for (int i = 0; i < 8; ++i)
#pragma unroll
        for (int j = 0; j < 8; ++j) acc[i][j] = 0.f;

    for (int k0 = 0; k0 < K; k0 += 16) {
#pragma unroll
        for (int l = 0; l < 2; ++l) {
            int idx = tid + l * 256;       // 0..511
            int row = idx >> 2;            // 0..127
            int kc  = (idx & 3) << 2;      // 0,4,8,12
            float4 va = *reinterpret_cast<const float4*>(
                A + (size_t)(m0 + row) * K + k0 + kc);
            As[kc + 0][row] = va.x; As[kc + 1][row] = va.y;
            As[kc + 2][row] = va.z; As[kc + 3][row] = va.w;
            float4 vb = *reinterpret_cast<const float4*>(
                W + (size_t)(n0 + row) * K + k0 + kc);
            Bs[kc + 0][row] = vb.x; Bs[kc + 1][row] = vb.y;
            Bs[kc + 2][row] = vb.z; Bs[kc + 3][row] = vb.w;
        }
        __syncthreads();

#pragma unroll
        for (int k = 0; k < 16; ++k) {
            float4 a0 = *reinterpret_cast<const float4*>(&As[k][ty * 8]);
            float4 a1 = *reinterpret_cast<const float4*>(&As[k][ty * 8 + 4]);
            float4 b0 = *reinterpret_cast<const float4*>(&Bs[k][tx * 8]);
            float4 b1 = *reinterpret_cast<const float4*>(&Bs[k][tx * 8 + 4]);
            float a[8] = {a0.x, a0.y, a0.z, a0.w, a1.x, a1.y, a1.z, a1.w};
            float b[8] = {b0.x, b0.y, b0.z, b0.w, b1.x, b1.y, b1.z, b1.w};
#pragma unroll
            for (int i = 0; i < 8; ++i)
#pragma unroll
                for (int j = 0; j < 8; ++j)
                    acc[i][j] = fmaf(a[i], b[j], acc[i][j]);
        }
        __syncthreads();
    }

    if (MODE == 1) {
#pragma unroll
        for (int i = 0; i < 8; ++i) {
            int m = m0 + ty * 8 + i;
#pragma unroll
            for (int j = 0; j < 8; ++j) {
                int n = n0 + tx * 8 + j;
                out[(size_t)m * N + n] = acc[i][j] + bias[n];
            }
        }
    } else {
        // scatter into Q/K/V, layout ((b*H + h)*T + t)*64 + d
#pragma unroll
        for (int i = 0; i < 8; ++i) {
            int m = m0 + ty * 8 + i;
            int t = m >> 3;      // / B
            int b = m & 7;       // % B
#pragma unroll
            for (int j = 0; j < 8; ++j) {
                int n = n0 + tx * 8 + j;
                float v = acc[i][j] + bias[n];
                int which = n >> 10;        // 0=q, 1=k, 2=v (uniform per block)
                int h = (n >> 6) & 15;
                int d = n & 63;
                size_t off = ((size_t)(b * Hh + h) * Tt + t) * HD + d;
                if (which == 0)      g_Q[off] = v * 0.125f;
                else if (which == 1) g_K[off] = v;
                else                 g_V[off] = v;
            }
        }
    }
}

// ---------------------------------------------------------------------------
// Fused attention: one thread per query row, online softmax.
// Block = 128 threads = 128 rows; grid = (B*H, T/128).
// K/V tiles of 64 rows staged in smem; rel_pos_bias streamed from gmem.
// ---------------------------------------------------------------------------
__global__ __launch_bounds__(128)
void attn_kernel(const float* __restrict__ rpb)
{
    __shared__ float4 Ks[64][16];   // 16 KB
    __shared__ float4 Vs[64][16];   // 16 KB

    const int bh = blockIdx.x;          // b*H + h
    const int h  = bh & 15;
    const int b  = bh >> 4;
    const int t  = blockIdx.y * 128 + threadIdx.x;

    const float4* qp = reinterpret_cast<const float4*>(
        g_Q + ((size_t)bh * Tt + t) * HD);
    float4 q[16];
#pragma unroll
    for (int i = 0; i < 16; ++i) q[i] = qp[i];

    float4 acc[16];
#pragma unroll
    for (int i = 0; i < 16; ++i) acc[i] = make_float4(0.f, 0.f, 0.f, 0.f);
    float mrun = -1e30f, lrun = 0.f;

    const float* bptr = rpb + ((size_t)h * Tt + t) * Tt;

    for (int s0 = 0; s0 < Tt; s0 += 64) {
        const float4* Kg = reinterpret_cast<const float4*>(
            g_K + ((size_t)bh * Tt + s0) * HD);
        const float4* Vg = reinterpret_cast<const float4*>(
            g_V + ((size_t)bh * Tt + s0) * HD);
#pragma unroll
        for (int l = 0; l < 8; ++l) {
            int idx = threadIdx.x + l * 128;
            reinterpret_cast<float4*>(Ks)[idx] = Kg[idx];
            reinterpret_cast<float4*>(Vs)[idx] = Vg[idx];
        }
        __syncthreads();

#pragma unroll
        for (int c0 = 0; c0 < 64; c0 += 32) {
            float sc[32];
#pragma unroll
            for (int j = 0; j < 32; ++j) {
                float s = 0.f;
#pragma unroll
                for (int d = 0; d < 16; ++d) {
                    float4 kk = Ks[c0 + j][d];   // broadcast LDS.128
                    s = fmaf(q[d].x, kk.x, s);
                    s = fmaf(q[d].y, kk.y, s);
                    s = fmaf(q[d].z, kk.z, s);
                    s = fmaf(q[d].w, kk.w, s);
                }
                sc[j] = s;
            }
#pragma unroll
            for (int j4 = 0; j4 < 8; ++j4) {
                float4 bb = *reinterpret_cast<const float4*>(
                    bptr + s0 + c0 + j4 * 4);
                sc[j4 * 4 + 0] += bb.x;
                sc[j4 * 4 + 1] += bb.y;
                sc[j4 * 4 + 2] += bb.z;
                sc[j4 * 4 + 3] += bb.w;
            }
            float tmax = mrun;
#pragma unroll
            for (int j = 0; j < 32; ++j) tmax = fmaxf(tmax, sc[j]);
            float corr = __expf(mrun - tmax);
            mrun = tmax;
            float psum = 0.f;
#pragma unroll
            for (int j = 0; j < 32; ++j) {
                sc[j] = __expf(sc[j] - tmax);
                psum += sc[j];
            }
            lrun = lrun * corr + psum;
#pragma unroll
            for (int d = 0; d < 16; ++d) {
                acc[d].x *= corr; acc[d].y *= corr;
                acc[d].z *= corr; acc[d].w *= corr;
            }
#pragma unroll
            for (int j = 0; j < 32; ++j) {
                float p = sc[j];
#pragma unroll
                for (int d = 0; d < 16; ++d) {
                    float4 vv = Vs[c0 + j][d];   // broadcast LDS.128
                    acc[d].x = fmaf(p, vv.x, acc[d].x);
                    acc[d].y = fmaf(p, vv.y, acc[d].y);
                    acc[d].z = fmaf(p, vv.z, acc[d].z);
                    acc[d].w = fmaf(p, vv.w, acc[d].w);
                }
            }
        }
        __syncthreads();
    }

    float inv = 1.f / lrun;
    // out layout (t, b, e): e = h*64 + d
    float4* op = reinterpret_cast<float4*>(
        g_AO + ((size_t)t * Bb + b) * Ee + h * HD);
#pragma unroll
    for (int d = 0; d < 16; ++d) {
        float4 r;
        r.x = acc[d].x * inv; r.y = acc[d].y * inv;
        r.z = acc[d].z * inv; r.w = acc[d].w * inv;
        op[d] = r;
    }
}

// ---------------------------------------------------------------------------
// Inputs (metadata order):
//  0 query (T,B,E) f32        5 out_proj_weight (E,E)
//  1 in_proj_weight (3E,E)    6 out_proj_bias (E)
//  2 in_proj_bias (3E)        7 out_left (E,R)
//  3 in_left (3E,R)           8 out_right (R,E)
//  4 in_right (R,E)           9 rel_pos_bias (H,T,T)
// ---------------------------------------------------------------------------
extern "C" void kernel_launch(void* const* d_in, const int* in_sizes, int n_in,
                              void* d_out, int out_size)
{
    const float* query = (const float*)d_in[0];
    const float* ipw   = (const float*)d_in[1];
    const float* ipb   = (const float*)d_in[2];
    const float* il    = (const float*)d_in[3];
    const float* ir    = (const float*)d_in[4];
    const float* opw   = (const float*)d_in[5];
    const float* opb   = (const float*)d_in[6];
    const float* ol    = (const float*)d_in[7];
    const float* orr   = (const float*)d_in[8];
    const float* rpb   = (const float*)d_in[9];
    float* out = (float*)d_out;

    weff_kernel<0><<<(F3 * Ee + 255) / 256, 256>>>(ipw, il, ir);
    weff_kernel<1><<<(Ee * Ee + 255) / 256, 256>>>(opw, ol, orr);

    gemm128<0><<<dim3(F3 / 128, Nrows / 128), 256>>>(
        query, ipb, nullptr, Nrows, F3, Ee);

    attn_kernel<<<dim3(Bb * Hh, Tt / 128), 128>>>(rpb);

    gemm128<1><<<dim3(Ee / 128, Nrows / 128), 256>>>(
        nullptr, opb, out, Nrows, Ee, Ee);
}

// round 3
// speedup vs baseline: 1.3744x; 1.3744x over previous
#include <cuda_runtime.h>
#include <cuda_bf16.h>
#include <cstdint>

// ---------------------------------------------------------------------------
// MultiheadAttention with low-rank-augmented in/out projections.
// T=1024, B=8, E=1024, H=16, R=16, HD=64.
//
// R2: projection GEMMs on tensor pipe via baseline-PTX mma.sync bf16
//     (m16n8k16) with 2-term bf16 split (hi/lo) for fp32-grade accuracy.
//     tcgen05 is unavailable: harness PTX target is sm_103 (non-'a').
// Attention stays fp32 SIMT (next round's target).
// ---------------------------------------------------------------------------

namespace {
constexpr int Tt = 1024;
constexpr int Bb = 8;
constexpr int Ee = 1024;
constexpr int Hh = 16;
constexpr int Rr = 16;
constexpr int HD = 64;
constexpr int F3 = 3 * Ee;          // 3072
constexpr int Nrows = Tt * Bb;      // 8192
constexpr int BM = 128, BN = 128, BK = 32;
}

// Scratch (device globals; no runtime allocation).
__device__ __align__(16) __nv_bfloat16 g_Win_h[F3 * Ee];
__device__ __align__(16) __nv_bfloat16 g_Win_l[F3 * Ee];
__device__ __align__(16) __nv_bfloat16 g_Wout_h[Ee * Ee];
__device__ __align__(16) __nv_bfloat16 g_Wout_l[Ee * Ee];
__device__ __align__(16) __nv_bfloat16 g_Ah[Nrows * Ee];
__device__ __align__(16) __nv_bfloat16 g_Al[Nrows * Ee];
__device__ __align__(16) __nv_bfloat16 g_AOh[Nrows * Ee];
__device__ __align__(16) __nv_bfloat16 g_AOl[Nrows * Ee];
__device__ __align__(16) float g_Q[Bb * Hh * Tt * HD];
__device__ __align__(16) float g_K[Bb * Hh * Tt * HD];
__device__ __align__(16) float g_V[Bb * Hh * Tt * HD];

// ---------------------------------------------------------------------------
__device__ __forceinline__ uint32_t smem_u32(const void* p) {
    uint32_t a;
    asm("{ .reg .u64 t; cvta.to.shared.u64 t, %1; cvt.u32.u64 %0, t; }"
        : "=r"(a) : "l"(p));
    return a;
}

__device__ __forceinline__ void split_bf(float x, __nv_bfloat16& h, __nv_bfloat16& l) {
    h = __float2bfloat16(x);
    l = __float2bfloat16(x - __bfloat162float(h));
}

#define LDSM4(R, A)                                                           \
    asm volatile("ldmatrix.sync.aligned.m8n8.x4.shared.b16 {%0,%1,%2,%3}, [%4];" \
                 : "=r"((R)[0]), "=r"((R)[1]), "=r"((R)[2]), "=r"((R)[3])     \
                 : "r"(A))

#define MMA16816(C, A, B)                                                     \
    asm volatile("mma.sync.aligned.m16n8k16.row.col.f32.bf16.bf16.f32 "       \
                 "{%0,%1,%2,%3}, {%4,%5,%6,%7}, {%8,%9}, {%0,%1,%2,%3};"      \
                 : "+f"((C)[0]), "+f"((C)[1]), "+f"((C)[2]), "+f"((C)[3])     \
                 : "r"((A)[0]), "r"((A)[1]), "r"((A)[2]), "r"((A)[3]),        \
                   "r"((B)[0]), "r"((B)[1]))

// ---------------------------------------------------------------------------
// W_eff = W + L@R, written as bf16 hi/lo split.
// ---------------------------------------------------------------------------
template <int WHICH>
__global__ void weff_kernel(const float* __restrict__ W,
                            const float* __restrict__ L,
                            const float* __restrict__ Rm)
{
    const int F = (WHICH == 0) ? F3 : Ee;
    __nv_bfloat16* oh = (WHICH == 0) ? g_Win_h : g_Wout_h;
    __nv_bfloat16* ol = (WHICH == 0) ? g_Win_l : g_Wout_l;
    int idx = blockIdx.x * 256 + threadIdx.x;
    if (idx >= F * Ee) return;
    int f = idx >> 10;
    int e = idx & 1023;
    float s = W[idx];
#pragma unroll
    for (int r = 0; r < Rr; ++r)
        s = fmaf(L[f * Rr + r], Rm[r * Ee + e], s);
    __nv_bfloat16 h, l;
    split_bf(s, h, l);
    oh[idx] = h;
    ol[idx] = l;
}

// ---------------------------------------------------------------------------
// Split query (fp32) into bf16 hi/lo.
// ---------------------------------------------------------------------------
__global__ void qsplit_kernel(const float* __restrict__ q)
{
    int idx = (blockIdx.x * 256 + threadIdx.x) * 4;
    float4 v = *reinterpret_cast<const float4*>(q + idx);
    __nv_bfloat16 h0, h1, h2, h3, l0, l1, l2, l3;
    split_bf(v.x, h0, l0); split_bf(v.y, h1, l1);
    split_bf(v.z, h2, l2); split_bf(v.w, h3, l3);
    __nv_bfloat162* ph = reinterpret_cast<__nv_bfloat162*>(g_Ah + idx);
    __nv_bfloat162* pl = reinterpret_cast<__nv_bfloat162*>(g_Al + idx);
    ph[0] = __nv_bfloat162(h0, h1); ph[1] = __nv_bfloat162(h2, h3);
    pl[0] = __nv_bfloat162(l0, l1); pl[1] = __nv_bfloat162(l2, l3);
}

// ---------------------------------------------------------------------------
// Tensor-pipe GEMM via mma.sync bf16 split: C = A·W^T + bias.
// A [M,K] (hi/lo bf16), W [N,K] (hi/lo bf16). Tile 128x128x32. 256 threads.
// Warp grid 2x4, warp tile 64x32, mma m16n8k16, 3 mmas per (mt,nt,k16).
// smem: per stage 4 matrices of 128x32 bf16, XOR-swizzled 16B chunks.
// MODE 0: A=g_Ah/l, W=g_Win_h/l -> scatter Q/K/V (q scaled 0.125)
// MODE 1: A=g_AOh/l, W=g_Wout_h/l -> out row-major + bias
// ---------------------------------------------------------------------------
template <int MODE>
__global__ __launch_bounds__(256, 1)
void gemm_mma(const float* __restrict__ bias, float* __restrict__ out,
              int N, int K)
{
    extern __shared__ __align__(16) char sm[];
    const __nv_bfloat16* Agh = (MODE == 0) ? g_Ah : g_AOh;
    const __nv_bfloat16* Agl = (MODE == 0) ? g_Al : g_AOl;
    const __nv_bfloat16* Bgh = (MODE == 0) ? g_Win_h : g_Wout_h;
    const __nv_bfloat16* Bgl = (MODE == 0) ? g_Win_l : g_Wout_l;

    const int tid  = threadIdx.x;
    const int lane = tid & 31;
    const int wid  = tid >> 5;
    const int wm   = wid >> 2;        // 0..1
    const int wn   = wid & 3;         // 0..3
    const int m0 = blockIdx.y * BM;
    const int n0 = blockIdx.x * BN;

    const uint32_t smb = smem_u32(sm);
    // stage layout (bytes): Ah 0, Al 8192, Bh 16384, Bl 24576; stage stride 32768
    const int MATB = 8192;

    float acc[4][4][4];
#pragma unroll
    for (int a = 0; a < 4; ++a)
#pragma unroll
        for (int b = 0; b < 4; ++b)
#pragma unroll
            for (int c = 0; c < 4; ++c) acc[a][b][c] = 0.f;

    // prefetch regs: [mat 0..3][j 0..1], mat: Ah,Al,Bh,Bl
    uint4 pf[4][2];

    const int row_[2] = { tid >> 2, (tid + 256) >> 2 };
    const int c8_[2]  = { tid & 3, (tid + 256) & 3 };

    // ---- load chunk 0
    {
        const int c = 0;
#pragma unroll
        for (int j = 0; j < 2; ++j) {
            size_t ao = (size_t)(m0 + row_[j]) * K + c * 32 + c8_[j] * 8;
            size_t bo = (size_t)(n0 + row_[j]) * K + c * 32 + c8_[j] * 8;
            pf[0][j] = *reinterpret_cast<const uint4*>(Agh + ao);
            pf[1][j] = *reinterpret_cast<const uint4*>(Agl + ao);
            pf[2][j] = *reinterpret_cast<const uint4*>(Bgh + bo);
            pf[3][j] = *reinterpret_cast<const uint4*>(Bgl + bo);
        }
    }

    const int nchunk = K / BK;
    for (int c = 0; c < nchunk; ++c) {
        // ---- store prefetched regs into stage c&1
        {
            uint32_t stb = smb + (uint32_t)(c & 1) * 32768;
#pragma unroll
            for (int j = 0; j < 2; ++j) {
                int row = row_[j], c8 = c8_[j];
                uint32_t off = (uint32_t)(row * 64 + ((c8 ^ ((row >> 1) & 3)) << 4));
#pragma unroll
                for (int mmat = 0; mmat < 4; ++mmat) {
                    *reinterpret_cast<uint4*>(sm + (stb - smb) + mmat * MATB + off)
                        = pf[mmat][j];
                }
            }
        }
        __syncthreads();

        // ---- prefetch next chunk
        if (c + 1 < nchunk) {
#pragma unroll
            for (int j = 0; j < 2; ++j) {
                size_t ao = (size_t)(m0 + row_[j]) * K + (c + 1) * 32 + c8_[j] * 8;
                size_t bo = (size_t)(n0 + row_[j]) * K + (c + 1) * 32 + c8_[j] * 8;
                pf[0][j] = *reinterpret_cast<const uint4*>(Agh + ao);
                pf[1][j] = *reinterpret_cast<const uint4*>(Agl + ao);
                pf[2][j] = *reinterpret_cast<const uint4*>(Bgh + bo);
                pf[3][j] = *reinterpret_cast<const uint4*>(Bgl + bo);
            }
        }

        // ---- compute 2 k16-steps from stage c&1
        {
            uint32_t stb = smb + (uint32_t)(c & 1) * 32768;
            const int g = lane >> 3, i = lane & 7;
#pragma unroll
            for (int ks = 0; ks < 2; ++ks) {
                uint32_t ah[4][4], al[4][4];
                const int arow_off = i + ((g & 1) << 3);
                const int akc = ks * 2 + (g >> 1);
#pragma unroll
                for (int mt = 0; mt < 4; ++mt) {
                    int row = wm * 64 + mt * 16 + arow_off;
                    uint32_t off = (uint32_t)(row * 64 + ((akc ^ ((row >> 1) & 3)) << 4));
                    LDSM4(ah[mt], stb + off);
                    LDSM4(al[mt], stb + MATB + off);
                }
                uint32_t bh[4][2], bl[4][2];
                const int brow_off = i + ((g >> 1) << 3);
                const int bkc = ks * 2 + (g & 1);
#pragma unroll
                for (int np = 0; np < 2; ++np) {
                    int row = wn * 32 + np * 16 + brow_off;
                    uint32_t off = (uint32_t)(row * 64 + ((bkc ^ ((row >> 1) & 3)) << 4));
                    uint32_t r4[4];
                    LDSM4(r4, stb + 2 * MATB + off);
                    bh[np * 2][0] = r4[0]; bh[np * 2][1] = r4[1];
                    bh[np * 2 + 1][0] = r4[2]; bh[np * 2 + 1][1] = r4[3];
                    LDSM4(r4, stb + 3 * MATB + off);
                    bl[np * 2][0] = r4[0]; bl[np * 2][1] = r4[1];
                    bl[np * 2 + 1][0] = r4[2]; bl[np * 2 + 1][1] = r4[3];
                }
#pragma unroll
                for (int mt = 0; mt < 4; ++mt)
#pragma unroll
                    for (int nb = 0; nb < 4; ++nb) {
                        MMA16816(acc[mt][nb], ah[mt], bh[nb]);
                        MMA16816(acc[mt][nb], ah[mt], bl[nb]);
                        MMA16816(acc[mt][nb], al[mt], bh[nb]);
                    }
            }
        }
        __syncthreads();
    }

    // ---- epilogue
    const int r = lane >> 2, tg = lane & 3;
#pragma unroll
    for (int mt = 0; mt < 4; ++mt) {
#pragma unroll
        for (int nb = 0; nb < 4; ++nb) {
            int m = m0 + wm * 64 + mt * 16 + r;
            int n = n0 + wn * 32 + nb * 8 + tg * 2;
            float2 bb = *reinterpret_cast<const float2*>(bias + n);
#pragma unroll
            for (int half = 0; half < 2; ++half) {
                int mm = m + half * 8;
                float v0 = acc[mt][nb][half * 2 + 0] + bb.x;
                float v1 = acc[mt][nb][half * 2 + 1] + bb.y;
                if (MODE == 1) {
                    float2 vv = {v0, v1};
                    *reinterpret_cast<float2*>(out + (size_t)mm * N + n) = vv;
                } else {
                    int t = mm >> 3;        // / B
                    int b = mm & 7;         // % B
                    int which = n >> 10;    // 0=q 1=k 2=v
                    int h = (n >> 6) & 15;
                    int d = n & 63;
                    float sc = (which == 0) ? 0.125f : 1.0f;
                    float* base = (which == 0) ? g_Q : (which == 1) ? g_K : g_V;
                    size_t off = ((size_t)(b * Hh + h) * Tt + t) * HD + d;
                    float2 vv = {v0 * sc, v1 * sc};
                    *reinterpret_cast<float2*>(base + off) = vv;
                }
            }
        }
    }
}

// ---------------------------------------------------------------------------
// Fused attention: one thread per query row, online softmax.
// Epilogue writes bf16 hi/lo for the out-projection GEMM.
// ---------------------------------------------------------------------------
__global__ __launch_bounds__(128)
void attn_kernel(const float* __restrict__ rpb)
{
    __shared__ float4 Ks[64][16];
    __shared__ float4 Vs[64][16];

    const int bh = blockIdx.x;
    const int h  = bh & 15;
    const int b  = bh >> 4;
    const int t  = blockIdx.y * 128 + threadIdx.x;

    const float4* qp = reinterpret_cast<const float4*>(
        g_Q + ((size_t)bh * Tt + t) * HD);
    float4 q[16];
#pragma unroll
    for (int i = 0; i < 16; ++i) q[i] = qp[i];

    float4 acc[16];
#pragma unroll
    for (int i = 0; i < 16; ++i) acc[i] = make_float4(0.f, 0.f, 0.f, 0.f);
    float mrun = -1e30f, lrun = 0.f;

    const float* bptr = rpb + ((size_t)h * Tt + t) * Tt;

    for (int s0 = 0; s0 < Tt; s0 += 64) {
        const float4* Kg = reinterpret_cast<const float4*>(
            g_K + ((size_t)bh * Tt + s0) * HD);
        const float4* Vg = reinterpret_cast<const float4*>(
            g_V + ((size_t)bh * Tt + s0) * HD);
#pragma unroll
        for (int l = 0; l < 8; ++l) {
            int idx = threadIdx.x + l * 128;
            reinterpret_cast<float4*>(Ks)[idx] = Kg[idx];
            reinterpret_cast<float4*>(Vs)[idx] = Vg[idx];
        }
        __syncthreads();

#pragma unroll
        for (int c0 = 0; c0 < 64; c0 += 32) {
            float sc[32];
#pragma unroll
            for (int j = 0; j < 32; ++j) {
                float s = 0.f;
#pragma unroll
                for (int d = 0; d < 16; ++d) {
                    float4 kk = Ks[c0 + j][d];
                    s = fmaf(q[d].x, kk.x, s);
                    s = fmaf(q[d].y, kk.y, s);
                    s = fmaf(q[d].z, kk.z, s);
                    s = fmaf(q[d].w, kk.w, s);
                }
                sc[j] = s;
            }
#pragma unroll
            for (int j4 = 0; j4 < 8; ++j4) {
                float4 bb = *reinterpret_cast<const float4*>(
                    bptr + s0 + c0 + j4 * 4);
                sc[j4 * 4 + 0] += bb.x;
                sc[j4 * 4 + 1] += bb.y;
                sc[j4 * 4 + 2] += bb.z;
                sc[j4 * 4 + 3] += bb.w;
            }
            float tmax = mrun;
#pragma unroll
            for (int j = 0; j < 32; ++j) tmax = fmaxf(tmax, sc[j]);
            float corr = __expf(mrun - tmax);
            mrun = tmax;
            float psum = 0.f;
#pragma unroll
            for (int j = 0; j < 32; ++j) {
                sc[j] = __expf(sc[j] - tmax);
                psum += sc[j];
            }
            lrun = lrun * corr + psum;
#pragma unroll
            for (int d = 0; d < 16; ++d) {
                acc[d].x *= corr; acc[d].y *= corr;
                acc[d].z *= corr; acc[d].w *= corr;
            }
#pragma unroll
            for (int j = 0; j < 32; ++j) {
                float p = sc[j];
#pragma unroll
                for (int d = 0; d < 16; ++d) {
                    float4 vv = Vs[c0 + j][d];
                    acc[d].x = fmaf(p, vv.x, acc[d].x);
                    acc[d].y = fmaf(p, vv.y, acc[d].y);
                    acc[d].z = fmaf(p, vv.z, acc[d].z);
                    acc[d].w = fmaf(p, vv.w, acc[d].w);
                }
            }
        }
        __syncthreads();
    }

    float inv = 1.f / lrun;
    size_t base = ((size_t)t * Bb + b) * Ee + (size_t)h * HD;
    __nv_bfloat162* oph = reinterpret_cast<__nv_bfloat162*>(g_AOh + base);
    __nv_bfloat162* opl = reinterpret_cast<__nv_bfloat162*>(g_AOl + base);
#pragma unroll
    for (int d = 0; d < 16; ++d) {
        float v0 = acc[d].x * inv, v1 = acc[d].y * inv;
        float v2 = acc[d].z * inv, v3 = acc[d].w * inv;
        __nv_bfloat16 h0, h1, h2, h3, l0, l1, l2, l3;
        split_bf(v0, h0, l0); split_bf(v1, h1, l1);
        split_bf(v2, h2, l2); split_bf(v3, h3, l3);
        oph[d * 2 + 0] = __nv_bfloat162(h0, h1);
        oph[d * 2 + 1] = __nv_bfloat162(h2, h3);
        opl[d * 2 + 0] = __nv_bfloat162(l0, l1);
        opl[d * 2 + 1] = __nv_bfloat162(l2, l3);
    }
}

// ---------------------------------------------------------------------------
extern "C" void kernel_launch(void* const* d_in, const int* in_sizes, int n_in,
                              void* d_out, int out_size)
{
    const float* query = (const float*)d_in[0];
    const float* ipw   = (const float*)d_in[1];
    const float* ipb   = (const float*)d_in[2];
    const float* il    = (const float*)d_in[3];
    const float* ir    = (const float*)d_in[4];
    const float* opw   = (const float*)d_in[5];
    const float* opb   = (const float*)d_in[6];
    const float* ol    = (const float*)d_in[7];
    const float* orr   = (const float*)d_in[8];
    const float* rpb   = (const float*)d_in[9];
    float* out = (float*)d_out;

    static bool attr_set = false;
    if (!attr_set) {
        cudaFuncSetAttribute(gemm_mma<0>,
            cudaFuncAttributeMaxDynamicSharedMemorySize, 65536);
        cudaFuncSetAttribute(gemm_mma<1>,
            cudaFuncAttributeMaxDynamicSharedMemorySize, 65536);
        attr_set = true;
    }

    weff_kernel<0><<<(F3 * Ee + 255) / 256, 256>>>(ipw, il, ir);
    weff_kernel<1><<<(Ee * Ee + 255) / 256, 256>>>(opw, ol, orr);
    qsplit_kernel<<<Nrows * Ee / 1024, 256>>>(query);

    gemm_mma<0><<<dim3(F3 / BN, Nrows / BM), 256, 65536>>>(ipb, nullptr, F3, Ee);

    attn_kernel<<<dim3(Bb * Hh, Tt / 128), 128>>>(rpb);

    gemm_mma<1><<<dim3(Ee / BN, Nrows / BM), 256, 65536>>>(opb, out, Ee, Ee);
}

// round 4
// speedup vs baseline: 3.7133x; 2.7018x over previous
#include <cuda_runtime.h>
#include <cuda_bf16.h>
#include <cstdint>

// ---------------------------------------------------------------------------
// MultiheadAttention with low-rank-augmented in/out projections.
// T=1024, B=8, E=1024, H=16, R=16, HD=64.
//
// R4: attention moved to tensor pipe (flash-attention-2 with mma.sync bf16
//     hi/lo split, cp.async double-buffered K/V, ldmatrix.trans for V).
//     Projections stay on the R3 split-bf16 mma GEMM; in-proj epilogue now
//     writes Q/K/V as bf16 hi/lo directly.
// ---------------------------------------------------------------------------

namespace {
constexpr int Tt = 1024;
constexpr int Bb = 8;
constexpr int Ee = 1024;
constexpr int Hh = 16;
constexpr int Rr = 16;
constexpr int HD = 64;
constexpr int F3 = 3 * Ee;          // 3072
constexpr int Nrows = Tt * Bb;      // 8192
constexpr int BM = 128, BN = 128, BK = 32;
}

// Scratch (device globals; no runtime allocation).
__device__ __align__(16) __nv_bfloat16 g_Win_h[F3 * Ee];
__device__ __align__(16) __nv_bfloat16 g_Win_l[F3 * Ee];
__device__ __align__(16) __nv_bfloat16 g_Wout_h[Ee * Ee];
__device__ __align__(16) __nv_bfloat16 g_Wout_l[Ee * Ee];
__device__ __align__(16) __nv_bfloat16 g_Ah[Nrows * Ee];
__device__ __align__(16) __nv_bfloat16 g_Al[Nrows * Ee];
__device__ __align__(16) __nv_bfloat16 g_AOh[Nrows * Ee];
__device__ __align__(16) __nv_bfloat16 g_AOl[Nrows * Ee];
__device__ __align__(16) __nv_bfloat16 g_Qh[Bb * Hh * Tt * HD];
__device__ __align__(16) __nv_bfloat16 g_Ql[Bb * Hh * Tt * HD];
__device__ __align__(16) __nv_bfloat16 g_Kh[Bb * Hh * Tt * HD];
__device__ __align__(16) __nv_bfloat16 g_Kl[Bb * Hh * Tt * HD];
__device__ __align__(16) __nv_bfloat16 g_Vh[Bb * Hh * Tt * HD];
__device__ __align__(16) __nv_bfloat16 g_Vl[Bb * Hh * Tt * HD];

// ---------------------------------------------------------------------------
__device__ __forceinline__ uint32_t smem_u32(const void* p) {
    uint32_t a;
    asm("{ .reg .u64 t; cvta.to.shared.u64 t, %1; cvt.u32.u64 %0, t; }"
        : "=r"(a) : "l"(p));
    return a;
}

__device__ __forceinline__ void split_bf(float x, __nv_bfloat16& h, __nv_bfloat16& l) {
    h = __float2bfloat16(x);
    l = __float2bfloat16(x - __bfloat162float(h));
}

#define LDSM4(R, A)                                                           \
    asm volatile("ldmatrix.sync.aligned.m8n8.x4.shared.b16 {%0,%1,%2,%3}, [%4];" \
                 : "=r"((R)[0]), "=r"((R)[1]), "=r"((R)[2]), "=r"((R)[3])     \
                 : "r"(A))

#define LDSM4T(R, A)                                                          \
    asm volatile("ldmatrix.sync.aligned.m8n8.x4.trans.shared.b16 {%0,%1,%2,%3}, [%4];" \
                 : "=r"((R)[0]), "=r"((R)[1]), "=r"((R)[2]), "=r"((R)[3])     \
                 : "r"(A))

#define MMA16816(C, A, B)                                                     \
    asm volatile("mma.sync.aligned.m16n8k16.row.col.f32.bf16.bf16.f32 "       \
                 "{%0,%1,%2,%3}, {%4,%5,%6,%7}, {%8,%9}, {%0,%1,%2,%3};"      \
                 : "+f"((C)[0]), "+f"((C)[1]), "+f"((C)[2]), "+f"((C)[3])     \
                 : "r"((A)[0]), "r"((A)[1]), "r"((A)[2]), "r"((A)[3]),        \
                   "r"((B)[0]), "r"((B)[1]))

#define CPASYNC16(D, S)                                                       \
    asm volatile("cp.async.cg.shared.global [%0], [%1], 16;"                  \
                 :: "r"(D), "l"(S))

// ---------------------------------------------------------------------------
// W_eff = W + L@R, written as bf16 hi/lo split.
// ---------------------------------------------------------------------------
template <int WHICH>
__global__ void weff_kernel(const float* __restrict__ W,
                            const float* __restrict__ L,
                            const float* __restrict__ Rm)
{
    const int F = (WHICH == 0) ? F3 : Ee;
    __nv_bfloat16* oh = (WHICH == 0) ? g_Win_h : g_Wout_h;
    __nv_bfloat16* ol = (WHICH == 0) ? g_Win_l : g_Wout_l;
    int idx = blockIdx.x * 256 + threadIdx.x;
    if (idx >= F * Ee) return;
    int f = idx >> 10;
    int e = idx & 1023;
    float s = W[idx];
#pragma unroll
    for (int r = 0; r < Rr; ++r)
        s = fmaf(L[f * Rr + r], Rm[r * Ee + e], s);
    __nv_bfloat16 h, l;
    split_bf(s, h, l);
    oh[idx] = h;
    ol[idx] = l;
}

// ---------------------------------------------------------------------------
// Split query (fp32) into bf16 hi/lo.
// ---------------------------------------------------------------------------
__global__ void qsplit_kernel(const float* __restrict__ q)
{
    int idx = (blockIdx.x * 256 + threadIdx.x) * 4;
    float4 v = *reinterpret_cast<const float4*>(q + idx);
    __nv_bfloat16 h0, h1, h2, h3, l0, l1, l2, l3;
    split_bf(v.x, h0, l0); split_bf(v.y, h1, l1);
    split_bf(v.z, h2, l2); split_bf(v.w, h3, l3);
    __nv_bfloat162* ph = reinterpret_cast<__nv_bfloat162*>(g_Ah + idx);
    __nv_bfloat162* pl = reinterpret_cast<__nv_bfloat162*>(g_Al + idx);
    ph[0] = __nv_bfloat162(h0, h1); ph[1] = __nv_bfloat162(h2, h3);
    pl[0] = __nv_bfloat162(l0, l1); pl[1] = __nv_bfloat162(l2, l3);
}

// ---------------------------------------------------------------------------
// Tensor-pipe GEMM via mma.sync bf16 split: C = A·W^T + bias.
// MODE 0: scatter to Q/K/V bf16 hi/lo (q scaled 0.125)
// MODE 1: out row-major fp32 + bias
// ---------------------------------------------------------------------------
template <int MODE>
__global__ __launch_bounds__(256, 1)
void gemm_mma(const float* __restrict__ bias, float* __restrict__ out,
              int N, int K)
{
    extern __shared__ __align__(16) char sm[];
    const __nv_bfloat16* Agh = (MODE == 0) ? g_Ah : g_AOh;
    const __nv_bfloat16* Agl = (MODE == 0) ? g_Al : g_AOl;
    const __nv_bfloat16* Bgh = (MODE == 0) ? g_Win_h : g_Wout_h;
    const __nv_bfloat16* Bgl = (MODE == 0) ? g_Win_l : g_Wout_l;

    const int tid  = threadIdx.x;
    const int lane = tid & 31;
    const int wid  = tid >> 5;
    const int wm   = wid >> 2;
    const int wn   = wid & 3;
    const int m0 = blockIdx.y * BM;
    const int n0 = blockIdx.x * BN;

    const uint32_t smb = smem_u32(sm);
    const int MATB = 8192;

    float acc[4][4][4];
#pragma unroll
    for (int a = 0; a < 4; ++a)
#pragma unroll
        for (int b = 0; b < 4; ++b)
#pragma unroll
            for (int c = 0; c < 4; ++c) acc[a][b][c] = 0.f;

    uint4 pf[4][2];
    const int row_[2] = { tid >> 2, (tid + 256) >> 2 };
    const int c8_[2]  = { tid & 3, (tid + 256) & 3 };

    {
#pragma unroll
        for (int j = 0; j < 2; ++j) {
            size_t ao = (size_t)(m0 + row_[j]) * K + c8_[j] * 8;
            size_t bo = (size_t)(n0 + row_[j]) * K + c8_[j] * 8;
            pf[0][j] = *reinterpret_cast<const uint4*>(Agh + ao);
            pf[1][j] = *reinterpret_cast<const uint4*>(Agl + ao);
            pf[2][j] = *reinterpret_cast<const uint4*>(Bgh + bo);
            pf[3][j] = *reinterpret_cast<const uint4*>(Bgl + bo);
        }
    }

    const int nchunk = K / BK;
    for (int c = 0; c < nchunk; ++c) {
        {
            uint32_t stoff = (uint32_t)(c & 1) * 32768;
#pragma unroll
            for (int j = 0; j < 2; ++j) {
                int row = row_[j], c8 = c8_[j];
                uint32_t off = (uint32_t)(row * 64 + ((c8 ^ ((row >> 1) & 3)) << 4));
#pragma unroll
                for (int mmat = 0; mmat < 4; ++mmat) {
                    *reinterpret_cast<uint4*>(sm + stoff + mmat * MATB + off)
                        = pf[mmat][j];
                }
            }
        }
        __syncthreads();

        if (c + 1 < nchunk) {
#pragma unroll
            for (int j = 0; j < 2; ++j) {
                size_t ao = (size_t)(m0 + row_[j]) * K + (c + 1) * 32 + c8_[j] * 8;
                size_t bo = (size_t)(n0 + row_[j]) * K + (c + 1) * 32 + c8_[j] * 8;
                pf[0][j] = *reinterpret_cast<const uint4*>(Agh + ao);
                pf[1][j] = *reinterpret_cast<const uint4*>(Agl + ao);
                pf[2][j] = *reinterpret_cast<const uint4*>(Bgh + bo);
                pf[3][j] = *reinterpret_cast<const uint4*>(Bgl + bo);
            }
        }

        {
            uint32_t stb = smb + (uint32_t)(c & 1) * 32768;
            const int g = lane >> 3, i = lane & 7;
#pragma unroll
            for (int ks = 0; ks < 2; ++ks) {
                uint32_t ah[4][4], al[4][4];
                const int arow_off = i + ((g & 1) << 3);
                const int akc = ks * 2 + (g >> 1);
#pragma unroll
                for (int mt = 0; mt < 4; ++mt) {
                    int row = wm * 64 + mt * 16 + arow_off;
                    uint32_t off = (uint32_t)(row * 64 + ((akc ^ ((row >> 1) & 3)) << 4));
                    LDSM4(ah[mt], stb + off);
                    LDSM4(al[mt], stb + MATB + off);
                }
                uint32_t bh[4][2], bl[4][2];
                const int brow_off = i + ((g >> 1) << 3);
                const int bkc = ks * 2 + (g & 1);
#pragma unroll
                for (int np = 0; np < 2; ++np) {
                    int row = wn * 32 + np * 16 + brow_off;
                    uint32_t off = (uint32_t)(row * 64 + ((bkc ^ ((row >> 1) & 3)) << 4));
                    uint32_t r4[4];
                    LDSM4(r4, stb + 2 * MATB + off);
                    bh[np * 2][0] = r4[0]; bh[np * 2][1] = r4[1];
                    bh[np * 2 + 1][0] = r4[2]; bh[np * 2 + 1][1] = r4[3];
                    LDSM4(r4, stb + 3 * MATB + off);
                    bl[np * 2][0] = r4[0]; bl[np * 2][1] = r4[1];
                    bl[np * 2 + 1][0] = r4[2]; bl[np * 2 + 1][1] = r4[3];
                }
#pragma unroll
                for (int mt = 0; mt < 4; ++mt)
#pragma unroll
                    for (int nb = 0; nb < 4; ++nb) {
                        MMA16816(acc[mt][nb], ah[mt], bh[nb]);
                        MMA16816(acc[mt][nb], ah[mt], bl[nb]);
                        MMA16816(acc[mt][nb], al[mt], bh[nb]);
                    }
            }
        }
        __syncthreads();
    }

    const int r = lane >> 2, tg = lane & 3;
#pragma unroll
    for (int mt = 0; mt < 4; ++mt) {
#pragma unroll
        for (int nb = 0; nb < 4; ++nb) {
            int m = m0 + wm * 64 + mt * 16 + r;
            int n = n0 + wn * 32 + nb * 8 + tg * 2;
            float2 bb = *reinterpret_cast<const float2*>(bias + n);
#pragma unroll
            for (int half = 0; half < 2; ++half) {
                int mm = m + half * 8;
                float v0 = acc[mt][nb][half * 2 + 0] + bb.x;
                float v1 = acc[mt][nb][half * 2 + 1] + bb.y;
                if (MODE == 1) {
                    float2 vv = {v0, v1};
                    *reinterpret_cast<float2*>(out + (size_t)mm * N + n) = vv;
                } else {
                    int t = mm >> 3;
                    int b = mm & 7;
                    int which = n >> 10;
                    int h = (n >> 6) & 15;
                    int d = n & 63;
                    float sc = (which == 0) ? 0.125f : 1.0f;
                    float x = v0 * sc, y = v1 * sc;
                    __nv_bfloat16* bph = (which == 0) ? g_Qh : (which == 1) ? g_Kh : g_Vh;
                    __nv_bfloat16* bpl = (which == 0) ? g_Ql : (which == 1) ? g_Kl : g_Vl;
                    size_t off = ((size_t)(b * Hh + h) * Tt + t) * HD + d;
                    float2 vv = {x, y};
                    __nv_bfloat162 hh = __float22bfloat162_rn(vv);
                    *reinterpret_cast<__nv_bfloat162*>(bph + off) = hh;
                    float2 lo = {x - __bfloat162float(hh.x), y - __bfloat162float(hh.y)};
                    *reinterpret_cast<__nv_bfloat162*>(bpl + off) = __float22bfloat162_rn(lo);
                }
            }
        }
    }
}

// ---------------------------------------------------------------------------
// Flash attention on tensor pipe. Grid (bh=128, tq=8), 256 threads (8 warps).
// Warp owns 16 q-rows; KV chunks of 64, double-buffered via cp.async.
// smem: Q hi/lo 32KB @0; stages 32KB each @32768, @65536.
// Stage layout: Kh 0, Kl 8192, Vh 16384, Vl 24576.
// ---------------------------------------------------------------------------
__global__ __launch_bounds__(256, 1)
void attn_mma(const float* __restrict__ rpb)
{
    extern __shared__ __align__(16) char sm[];
    const int tid = threadIdx.x;
    const int lane = tid & 31;
    const int w = tid >> 5;
    const int bh = blockIdx.x;
    const int h = bh & 15, b = bh >> 4;
    const int t0 = blockIdx.y * 128;

    const uint32_t uQ = smem_u32(sm);
    const uint32_t uS0 = uQ + 32768;

    // ---- issue Q (hi+lo) and chunk0, then chunk1
    {
#pragma unroll
        for (int p = 0; p < 8; ++p) {
            int i = tid + p * 256;
            int half = i >> 10, rem = i & 1023;
            int row = rem >> 3, cc = rem & 7;
            const __nv_bfloat16* src = (half ? g_Ql : g_Qh)
                + ((size_t)bh * Tt + t0 + row) * HD + cc * 8;
            uint32_t dst = uQ + half * 16384 + row * 128 + (((cc ^ (row & 7))) << 4);
            CPASYNC16(dst, src);
        }
    }
    const __nv_bfloat16* kvsrc[4] = { g_Kh, g_Kl, g_Vh, g_Vl };
#define LOAD_CHUNK(CIDX, ST)                                                   \
    {                                                                          \
        const uint32_t base_ = uS0 + (uint32_t)(ST) * 32768;                   \
        int s0_ = (CIDX) * 64;                                                 \
        _Pragma("unroll")                                                      \
        for (int p = 0; p < 8; ++p) {                                          \
            int i = tid + p * 256;                                             \
            int tile = i >> 9;                                                 \
            int rem = i & 511;                                                 \
            int row = rem >> 3, cc = rem & 7;                                  \
            const __nv_bfloat16* src = kvsrc[tile]                             \
                + ((size_t)bh * Tt + s0_ + row) * HD + cc * 8;                 \
            uint32_t dst = base_ + tile * 8192 + row * 128                     \
                         + (((cc ^ (row & 7))) << 4);                          \
            CPASYNC16(dst, src);                                               \
        }                                                                      \
    }

    LOAD_CHUNK(0, 0);
    asm volatile("cp.async.commit_group;" ::: "memory");
    LOAD_CHUNK(1, 1);
    asm volatile("cp.async.commit_group;" ::: "memory");
    asm volatile("cp.async.wait_group 1;" ::: "memory");
    __syncthreads();

    // ---- persistent Q fragments (hi/lo), 4 k-steps
    uint32_t qfh[4][4], qfl[4][4];
    {
        int r = w * 16 + (lane & 15);
        uint32_t rb = uQ + r * 128;
#pragma unroll
        for (int kk = 0; kk < 4; ++kk) {
            uint32_t c = (uint32_t)(2 * kk + (lane >> 4));
            uint32_t off = ((c ^ (r & 7)) << 4);
            LDSM4(qfh[kk], rb + off);
            LDSM4(qfl[kk], rb + 16384 + off);
        }
    }

    float o[8][4];
#pragma unroll
    for (int j = 0; j < 8; ++j)
#pragma unroll
        for (int v = 0; v < 4; ++v) o[j][v] = 0.f;
    float m0r = -1e30f, m1r = -1e30f, l0r = 0.f, l1r = 0.f;

    const int rq = lane >> 2;
    const int cq = (lane & 3) * 2;
    const size_t brow0_base = ((size_t)h * Tt + (t0 + w * 16 + rq)) * Tt;
    const size_t brow1_base = brow0_base + 8 * (size_t)Tt;

    for (int c = 0; c < 16; ++c) {
        if (c == 15) asm volatile("cp.async.wait_group 0;" ::: "memory");
        else         asm volatile("cp.async.wait_group 1;" ::: "memory");
        __syncthreads();

        const uint32_t stb = uS0 + (uint32_t)(c & 1) * 32768;
        const int g = lane >> 3, i = lane & 7;

        // ---- scores S = Q·K^T (3-term split)
        float s[8][4];
#pragma unroll
        for (int j = 0; j < 8; ++j)
#pragma unroll
            for (int v = 0; v < 4; ++v) s[j][v] = 0.f;

#pragma unroll
        for (int kk = 0; kk < 4; ++kk) {
            uint32_t kbh[8][2], kbl[8][2];
            const int brow_off = i + ((g >> 1) << 3);
            const int bkc = kk * 2 + (g & 1);
#pragma unroll
            for (int ng = 0; ng < 4; ++ng) {
                int row = ng * 16 + brow_off;
                uint32_t off = (uint32_t)(row * 128 + ((bkc ^ (row & 7)) << 4));
                uint32_t r4[4];
                LDSM4(r4, stb + off);                 // Kh
                kbh[ng * 2][0] = r4[0]; kbh[ng * 2][1] = r4[1];
                kbh[ng * 2 + 1][0] = r4[2]; kbh[ng * 2 + 1][1] = r4[3];
                LDSM4(r4, stb + 8192 + off);          // Kl
                kbl[ng * 2][0] = r4[0]; kbl[ng * 2][1] = r4[1];
                kbl[ng * 2 + 1][0] = r4[2]; kbl[ng * 2 + 1][1] = r4[3];
            }
#pragma unroll
            for (int nt = 0; nt < 8; ++nt) {
                MMA16816(s[nt], qfh[kk], kbh[nt]);
                MMA16816(s[nt], qfh[kk], kbl[nt]);
                MMA16816(s[nt], qfl[kk], kbh[nt]);
            }
        }

        // ---- + rel_pos_bias
        {
            const float* bp0 = rpb + brow0_base + c * 64 + cq;
            const float* bp1 = rpb + brow1_base + c * 64 + cq;
#pragma unroll
            for (int j = 0; j < 8; ++j) {
                float2 b0 = *reinterpret_cast<const float2*>(bp0 + j * 8);
                float2 b1 = *reinterpret_cast<const float2*>(bp1 + j * 8);
                s[j][0] += b0.x; s[j][1] += b0.y;
                s[j][2] += b1.x; s[j][3] += b1.y;
            }
        }

        // ---- online softmax
        float cm0 = -1e30f, cm1 = -1e30f;
#pragma unroll
        for (int j = 0; j < 8; ++j) {
            cm0 = fmaxf(cm0, fmaxf(s[j][0], s[j][1]));
            cm1 = fmaxf(cm1, fmaxf(s[j][2], s[j][3]));
        }
        cm0 = fmaxf(cm0, __shfl_xor_sync(0xffffffffu, cm0, 1));
        cm0 = fmaxf(cm0, __shfl_xor_sync(0xffffffffu, cm0, 2));
        cm1 = fmaxf(cm1, __shfl_xor_sync(0xffffffffu, cm1, 1));
        cm1 = fmaxf(cm1, __shfl_xor_sync(0xffffffffu, cm1, 2));
        float m0n = fmaxf(m0r, cm0), m1n = fmaxf(m1r, cm1);
        float cor0 = __expf(m0r - m0n), cor1 = __expf(m1r - m1n);
        m0r = m0n; m1r = m1n;
        float rs0 = 0.f, rs1 = 0.f;
#pragma unroll
        for (int j = 0; j < 8; ++j) {
            s[j][0] = __expf(s[j][0] - m0n);
            s[j][1] = __expf(s[j][1] - m0n);
            s[j][2] = __expf(s[j][2] - m1n);
            s[j][3] = __expf(s[j][3] - m1n);
            rs0 += s[j][0] + s[j][1];
            rs1 += s[j][2] + s[j][3];
        }
        rs0 += __shfl_xor_sync(0xffffffffu, rs0, 1);
        rs0 += __shfl_xor_sync(0xffffffffu, rs0, 2);
        rs1 += __shfl_xor_sync(0xffffffffu, rs1, 1);
        rs1 += __shfl_xor_sync(0xffffffffu, rs1, 2);
        l0r = l0r * cor0 + rs0;
        l1r = l1r * cor1 + rs1;
#pragma unroll
        for (int j = 0; j < 8; ++j) {
            o[j][0] *= cor0; o[j][1] *= cor0;
            o[j][2] *= cor1; o[j][3] *= cor1;
        }

        // ---- P hi/lo fragments (registers only)
        uint32_t ph[8][2], pl[8][2];
#pragma unroll
        for (int j = 0; j < 8; ++j) {
            float2 v0 = {s[j][0], s[j][1]};
            __nv_bfloat162 hh0 = __float22bfloat162_rn(v0);
            ph[j][0] = *reinterpret_cast<uint32_t*>(&hh0);
            float2 lo0 = {s[j][0] - __bfloat162float(hh0.x),
                          s[j][1] - __bfloat162float(hh0.y)};
            __nv_bfloat162 ll0 = __float22bfloat162_rn(lo0);
            pl[j][0] = *reinterpret_cast<uint32_t*>(&ll0);
            float2 v1 = {s[j][2], s[j][3]};
            __nv_bfloat162 hh1 = __float22bfloat162_rn(v1);
            ph[j][1] = *reinterpret_cast<uint32_t*>(&hh1);
            float2 lo1 = {s[j][2] - __bfloat162float(hh1.x),
                          s[j][3] - __bfloat162float(hh1.y)};
            __nv_bfloat162 ll1 = __float22bfloat162_rn(lo1);
            pl[j][1] = *reinterpret_cast<uint32_t*>(&ll1);
        }

        // ---- O += P·V (3-term split), V via ldmatrix.trans
#pragma unroll
        for (int kk = 0; kk < 4; ++kk) {
            uint32_t a_h[4] = { ph[2*kk][0], ph[2*kk][1], ph[2*kk+1][0], ph[2*kk+1][1] };
            uint32_t a_l[4] = { pl[2*kk][0], pl[2*kk][1], pl[2*kk+1][0], pl[2*kk+1][1] };
            uint32_t vbh[8][2], vbl[8][2];
            const int srow = kk * 16 + i + ((g >> 1) << 3);
#pragma unroll
            for (int dg = 0; dg < 4; ++dg) {
                int ck = dg * 2 + (g & 1);
                uint32_t off = (uint32_t)(srow * 128 + ((ck ^ (srow & 7)) << 4));
                uint32_t r4[4];
                LDSM4T(r4, stb + 16384 + off);        // Vh
                vbh[dg * 2][0] = r4[0]; vbh[dg * 2][1] = r4[2];
                vbh[dg * 2 + 1][0] = r4[1]; vbh[dg * 2 + 1][1] = r4[3];
                LDSM4T(r4, stb + 24576 + off);        // Vl
                vbl[dg * 2][0] = r4[0]; vbl[dg * 2][1] = r4[2];
                vbl[dg * 2 + 1][0] = r4[1]; vbl[dg * 2 + 1][1] = r4[3];
            }
#pragma unroll
            for (int dt = 0; dt < 8; ++dt) {
                MMA16816(o[dt], a_h, vbh[dt]);
                MMA16816(o[dt], a_h, vbl[dt]);
                MMA16816(o[dt], a_l, vbh[dt]);
            }
        }

        __syncthreads();
        if (c + 2 < 16) {
            LOAD_CHUNK(c + 2, c & 1);
            asm volatile("cp.async.commit_group;" ::: "memory");
        }
    }

    // ---- epilogue: write bf16 hi/lo to g_AOh/g_AOl at (t, b, h*64+d)
    float inv0 = 1.f / l0r, inv1 = 1.f / l1r;
    int t_row0 = t0 + w * 16 + rq;
    int t_row1 = t_row0 + 8;
#pragma unroll
    for (int j = 0; j < 8; ++j) {
        int d = j * 8 + cq;
        size_t i0 = ((size_t)t_row0 * Bb + b) * Ee + h * HD + d;
        size_t i1 = ((size_t)t_row1 * Bb + b) * Ee + h * HD + d;
        float x0 = o[j][0] * inv0, y0 = o[j][1] * inv0;
        float x1 = o[j][2] * inv1, y1 = o[j][3] * inv1;
        float2 v0 = {x0, y0};
        __nv_bfloat162 hh0 = __float22bfloat162_rn(v0);
        *reinterpret_cast<__nv_bfloat162*>(g_AOh + i0) = hh0;
        float2 lo0 = {x0 - __bfloat162float(hh0.x), y0 - __bfloat162float(hh0.y)};
        *reinterpret_cast<__nv_bfloat162*>(g_AOl + i0) = __float22bfloat162_rn(lo0);
        float2 v1 = {x1, y1};
        __nv_bfloat162 hh1 = __float22bfloat162_rn(v1);
        *reinterpret_cast<__nv_bfloat162*>(g_AOh + i1) = hh1;
        float2 lo1 = {x1 - __bfloat162float(hh1.x), y1 - __bfloat162float(hh1.y)};
        *reinterpret_cast<__nv_bfloat162*>(g_AOl + i1) = __float22bfloat162_rn(lo1);
    }
#undef LOAD_CHUNK
}

// ---------------------------------------------------------------------------
extern "C" void kernel_launch(void* const* d_in, const int* in_sizes, int n_in,
                              void* d_out, int out_size)
{
    const float* query = (const float*)d_in[0];
    const float* ipw   = (const float*)d_in[1];
    const float* ipb   = (const float*)d_in[2];
    const float* il    = (const float*)d_in[3];
    const float* ir    = (const float*)d_in[4];
    const float* opw   = (const float*)d_in[5];
    const float* opb   = (const float*)d_in[6];
    const float* ol    = (const float*)d_in[7];
    const float* orr   = (const float*)d_in[8];
    const float* rpb   = (const float*)d_in[9];
    float* out = (float*)d_out;

    static bool attr_set = false;
    if (!attr_set) {
        cudaFuncSetAttribute(gemm_mma<0>,
            cudaFuncAttributeMaxDynamicSharedMemorySize, 65536);
        cudaFuncSetAttribute(gemm_mma<1>,
            cudaFuncAttributeMaxDynamicSharedMemorySize, 65536);
        cudaFuncSetAttribute(attn_mma,
            cudaFuncAttributeMaxDynamicSharedMemorySize, 98304);
        attr_set = true;
    }

    weff_kernel<0><<<(F3 * Ee + 255) / 256, 256>>>(ipw, il, ir);
    weff_kernel<1><<<(Ee * Ee + 255) / 256, 256>>>(opw, ol, orr);
    qsplit_kernel<<<Nrows * Ee / 1024, 256>>>(query);

    gemm_mma<0><<<dim3(F3 / BN, Nrows / BM), 256, 65536>>>(ipb, nullptr, F3, Ee);

    attn_mma<<<dim3(Bb * Hh, Tt / 128), 256, 98304>>>(rpb);

    gemm_mma<1><<<dim3(Ee / BN, Nrows / BM), 256, 65536>>>(opb, out, Ee, Ee);
}

// round 5
// speedup vs baseline: 3.8314x; 1.0318x over previous
#include <cuda_runtime.h>
#include <cuda_bf16.h>
#include <cstdint>

// ---------------------------------------------------------------------------
// MultiheadAttention with low-rank-augmented in/out projections.
// T=1024, B=8, E=1024, H=16, R=16, HD=64.
//
// R5: projection GEMMs rebuilt on a 4-stage cp.async pipeline (no STS
//     staging, one sync per K-chunk). Attention unchanged from R4.
// ---------------------------------------------------------------------------

namespace {
constexpr int Tt = 1024;
constexpr int Bb = 8;
constexpr int Ee = 1024;
constexpr int Hh = 16;
constexpr int Rr = 16;
constexpr int HD = 64;
constexpr int F3 = 3 * Ee;          // 3072
constexpr int Nrows = Tt * Bb;      // 8192
constexpr int BM = 128, BN = 128, BK = 32;
}

// Scratch (device globals; no runtime allocation).
__device__ __align__(16) __nv_bfloat16 g_Win_h[F3 * Ee];
__device__ __align__(16) __nv_bfloat16 g_Win_l[F3 * Ee];
__device__ __align__(16) __nv_bfloat16 g_Wout_h[Ee * Ee];
__device__ __align__(16) __nv_bfloat16 g_Wout_l[Ee * Ee];
__device__ __align__(16) __nv_bfloat16 g_Ah[Nrows * Ee];
__device__ __align__(16) __nv_bfloat16 g_Al[Nrows * Ee];
__device__ __align__(16) __nv_bfloat16 g_AOh[Nrows * Ee];
__device__ __align__(16) __nv_bfloat16 g_AOl[Nrows * Ee];
__device__ __align__(16) __nv_bfloat16 g_Qh[Bb * Hh * Tt * HD];
__device__ __align__(16) __nv_bfloat16 g_Ql[Bb * Hh * Tt * HD];
__device__ __align__(16) __nv_bfloat16 g_Kh[Bb * Hh * Tt * HD];
__device__ __align__(16) __nv_bfloat16 g_Kl[Bb * Hh * Tt * HD];
__device__ __align__(16) __nv_bfloat16 g_Vh[Bb * Hh * Tt * HD];
__device__ __align__(16) __nv_bfloat16 g_Vl[Bb * Hh * Tt * HD];

// ---------------------------------------------------------------------------
__device__ __forceinline__ uint32_t smem_u32(const void* p) {
    uint32_t a;
    asm("{ .reg .u64 t; cvta.to.shared.u64 t, %1; cvt.u32.u64 %0, t; }"
        : "=r"(a) : "l"(p));
    return a;
}

__device__ __forceinline__ void split_bf(float x, __nv_bfloat16& h, __nv_bfloat16& l) {
    h = __float2bfloat16(x);
    l = __float2bfloat16(x - __bfloat162float(h));
}

#define LDSM4(R, A)                                                           \
    asm volatile("ldmatrix.sync.aligned.m8n8.x4.shared.b16 {%0,%1,%2,%3}, [%4];" \
                 : "=r"((R)[0]), "=r"((R)[1]), "=r"((R)[2]), "=r"((R)[3])     \
                 : "r"(A))

#define LDSM4T(R, A)                                                          \
    asm volatile("ldmatrix.sync.aligned.m8n8.x4.trans.shared.b16 {%0,%1,%2,%3}, [%4];" \
                 : "=r"((R)[0]), "=r"((R)[1]), "=r"((R)[2]), "=r"((R)[3])     \
                 : "r"(A))

#define MMA16816(C, A, B)                                                     \
    asm volatile("mma.sync.aligned.m16n8k16.row.col.f32.bf16.bf16.f32 "       \
                 "{%0,%1,%2,%3}, {%4,%5,%6,%7}, {%8,%9}, {%0,%1,%2,%3};"      \
                 : "+f"((C)[0]), "+f"((C)[1]), "+f"((C)[2]), "+f"((C)[3])     \
                 : "r"((A)[0]), "r"((A)[1]), "r"((A)[2]), "r"((A)[3]),        \
                   "r"((B)[0]), "r"((B)[1]))

#define CPASYNC16(D, S)                                                       \
    asm volatile("cp.async.cg.shared.global [%0], [%1], 16;"                  \
                 :: "r"(D), "l"(S))

// ---------------------------------------------------------------------------
// W_eff = W + L@R, written as bf16 hi/lo split.
// ---------------------------------------------------------------------------
template <int WHICH>
__global__ void weff_kernel(const float* __restrict__ W,
                            const float* __restrict__ L,
                            const float* __restrict__ Rm)
{
    const int F = (WHICH == 0) ? F3 : Ee;
    __nv_bfloat16* oh = (WHICH == 0) ? g_Win_h : g_Wout_h;
    __nv_bfloat16* ol = (WHICH == 0) ? g_Win_l : g_Wout_l;
    int idx = blockIdx.x * 256 + threadIdx.x;
    if (idx >= F * Ee) return;
    int f = idx >> 10;
    int e = idx & 1023;
    float s = W[idx];
#pragma unroll
    for (int r = 0; r < Rr; ++r)
        s = fmaf(L[f * Rr + r], Rm[r * Ee + e], s);
    __nv_bfloat16 h, l;
    split_bf(s, h, l);
    oh[idx] = h;
    ol[idx] = l;
}

// ---------------------------------------------------------------------------
// Split query (fp32) into bf16 hi/lo.
// ---------------------------------------------------------------------------
__global__ void qsplit_kernel(const float* __restrict__ q)
{
    int idx = (blockIdx.x * 256 + threadIdx.x) * 4;
    float4 v = *reinterpret_cast<const float4*>(q + idx);
    __nv_bfloat16 h0, h1, h2, h3, l0, l1, l2, l3;
    split_bf(v.x, h0, l0); split_bf(v.y, h1, l1);
    split_bf(v.z, h2, l2); split_bf(v.w, h3, l3);
    __nv_bfloat162* ph = reinterpret_cast<__nv_bfloat162*>(g_Ah + idx);
    __nv_bfloat162* pl = reinterpret_cast<__nv_bfloat162*>(g_Al + idx);
    ph[0] = __nv_bfloat162(h0, h1); ph[1] = __nv_bfloat162(h2, h3);
    pl[0] = __nv_bfloat162(l0, l1); pl[1] = __nv_bfloat162(l2, l3);
}

// ---------------------------------------------------------------------------
// Tensor-pipe GEMM via mma.sync bf16 split: C = A·W^T + bias.
// 4-stage cp.async pipeline, 32KB/stage (Ah,Al,Bh,Bl 8KB each), 128KB smem.
// MODE 0: scatter to Q/K/V bf16 hi/lo (q scaled 0.125)
// MODE 1: out row-major fp32 + bias
// ---------------------------------------------------------------------------
template <int MODE>
__global__ __launch_bounds__(256, 1)
void gemm_mma(const float* __restrict__ bias, float* __restrict__ out,
              int N, int K)
{
    extern __shared__ __align__(16) char sm[];
    const __nv_bfloat16* Agh = (MODE == 0) ? g_Ah : g_AOh;
    const __nv_bfloat16* Agl = (MODE == 0) ? g_Al : g_AOl;
    const __nv_bfloat16* Bgh = (MODE == 0) ? g_Win_h : g_Wout_h;
    const __nv_bfloat16* Bgl = (MODE == 0) ? g_Win_l : g_Wout_l;

    const int tid  = threadIdx.x;
    const int lane = tid & 31;
    const int wid  = tid >> 5;
    const int wm   = wid >> 2;
    const int wn   = wid & 3;
    const int m0 = blockIdx.y * BM;
    const int n0 = blockIdx.x * BN;

    const uint32_t smb = smem_u32(sm);
    const int MATB = 8192;

    // per-thread load geometry: 8 x 16B chunks per stage
    const int mat_[8] = { (tid) >> 9 | 0, 0, 0, 0, 0, 0, 0, 0 };
    (void)mat_;

    float acc[4][4][4];
#pragma unroll
    for (int a = 0; a < 4; ++a)
#pragma unroll
        for (int b = 0; b < 4; ++b)
#pragma unroll
            for (int c = 0; c < 4; ++c) acc[a][b][c] = 0.f;

    const int nchunk = K / BK;

#define ISSUE_STAGE(CIDX)                                                     \
    {                                                                         \
        uint32_t base_ = smb + (uint32_t)((CIDX) & 3) * 32768;                \
        _Pragma("unroll")                                                     \
        for (int p = 0; p < 8; ++p) {                                         \
            int i = tid + p * 256;                                            \
            int mat = i >> 9;                                                 \
            int rem = i & 511;                                                \
            int row = rem >> 2, c8 = rem & 3;                                 \
            size_t go = (mat < 2)                                             \
                ? (size_t)(m0 + row) * K + (CIDX) * 32 + c8 * 8               \
                : (size_t)(n0 + row) * K + (CIDX) * 32 + c8 * 8;              \
            const __nv_bfloat16* src =                                        \
                (mat == 0 ? Agh : mat == 1 ? Agl : mat == 2 ? Bgh : Bgl) + go;\
            uint32_t dst = base_ + mat * MATB + row * 64                      \
                         + ((c8 ^ ((row >> 1) & 3)) << 4);                    \
            CPASYNC16(dst, src);                                              \
        }                                                                     \
        asm volatile("cp.async.commit_group;" ::: "memory");                  \
    }

    ISSUE_STAGE(0);
    ISSUE_STAGE(1);
    ISSUE_STAGE(2);

    for (int c = 0; c < nchunk; ++c) {
        asm volatile("cp.async.wait_group 2;" ::: "memory");
        __syncthreads();

        if (c + 3 < nchunk) ISSUE_STAGE(c + 3);

        {
            uint32_t stb = smb + (uint32_t)(c & 3) * 32768;
            const int g = lane >> 3, i = lane & 7;
#pragma unroll
            for (int ks = 0; ks < 2; ++ks) {
                uint32_t ah[4][4], al[4][4];
                const int arow_off = i + ((g & 1) << 3);
                const int akc = ks * 2 + (g >> 1);
#pragma unroll
                for (int mt = 0; mt < 4; ++mt) {
                    int row = wm * 64 + mt * 16 + arow_off;
                    uint32_t off = (uint32_t)(row * 64 + ((akc ^ ((row >> 1) & 3)) << 4));
                    LDSM4(ah[mt], stb + off);
                    LDSM4(al[mt], stb + MATB + off);
                }
                uint32_t bh[4][2], bl[4][2];
                const int brow_off = i + ((g >> 1) << 3);
                const int bkc = ks * 2 + (g & 1);
#pragma unroll
                for (int np = 0; np < 2; ++np) {
                    int row = wn * 32 + np * 16 + brow_off;
                    uint32_t off = (uint32_t)(row * 64 + ((bkc ^ ((row >> 1) & 3)) << 4));
                    uint32_t r4[4];
                    LDSM4(r4, stb + 2 * MATB + off);
                    bh[np * 2][0] = r4[0]; bh[np * 2][1] = r4[1];
                    bh[np * 2 + 1][0] = r4[2]; bh[np * 2 + 1][1] = r4[3];
                    LDSM4(r4, stb + 3 * MATB + off);
                    bl[np * 2][0] = r4[0]; bl[np * 2][1] = r4[1];
                    bl[np * 2 + 1][0] = r4[2]; bl[np * 2 + 1][1] = r4[3];
                }
#pragma unroll
                for (int mt = 0; mt < 4; ++mt)
#pragma unroll
                    for (int nb = 0; nb < 4; ++nb) {
                        MMA16816(acc[mt][nb], ah[mt], bh[nb]);
                        MMA16816(acc[mt][nb], ah[mt], bl[nb]);
                        MMA16816(acc[mt][nb], al[mt], bh[nb]);
                    }
            }
        }
        __syncthreads();
    }
#undef ISSUE_STAGE

    const int r = lane >> 2, tg = lane & 3;
#pragma unroll
    for (int mt = 0; mt < 4; ++mt) {
#pragma unroll
        for (int nb = 0; nb < 4; ++nb) {
            int m = m0 + wm * 64 + mt * 16 + r;
            int n = n0 + wn * 32 + nb * 8 + tg * 2;
            float2 bb = *reinterpret_cast<const float2*>(bias + n);
#pragma unroll
            for (int half = 0; half < 2; ++half) {
                int mm = m + half * 8;
                float v0 = acc[mt][nb][half * 2 + 0] + bb.x;
                float v1 = acc[mt][nb][half * 2 + 1] + bb.y;
                if (MODE == 1) {
                    float2 vv = {v0, v1};
                    *reinterpret_cast<float2*>(out + (size_t)mm * N + n) = vv;
                } else {
                    int t = mm >> 3;
                    int b = mm & 7;
                    int which = n >> 10;
                    int h = (n >> 6) & 15;
                    int d = n & 63;
                    float sc = (which == 0) ? 0.125f : 1.0f;
                    float x = v0 * sc, y = v1 * sc;
                    __nv_bfloat16* bph = (which == 0) ? g_Qh : (which == 1) ? g_Kh : g_Vh;
                    __nv_bfloat16* bpl = (which == 0) ? g_Ql : (which == 1) ? g_Kl : g_Vl;
                    size_t off = ((size_t)(b * Hh + h) * Tt + t) * HD + d;
                    float2 vv = {x, y};
                    __nv_bfloat162 hh = __float22bfloat162_rn(vv);
                    *reinterpret_cast<__nv_bfloat162*>(bph + off) = hh;
                    float2 lo = {x - __bfloat162float(hh.x), y - __bfloat162float(hh.y)};
                    *reinterpret_cast<__nv_bfloat162*>(bpl + off) = __float22bfloat162_rn(lo);
                }
            }
        }
    }
}

// ---------------------------------------------------------------------------
// Flash attention on tensor pipe (unchanged from R4).
// ---------------------------------------------------------------------------
__global__ __launch_bounds__(256, 1)
void attn_mma(const float* __restrict__ rpb)
{
    extern __shared__ __align__(16) char sm[];
    const int tid = threadIdx.x;
    const int lane = tid & 31;
    const int w = tid >> 5;
    const int bh = blockIdx.x;
    const int h = bh & 15, b = bh >> 4;
    const int t0 = blockIdx.y * 128;

    const uint32_t uQ = smem_u32(sm);
    const uint32_t uS0 = uQ + 32768;

    {
#pragma unroll
        for (int p = 0; p < 8; ++p) {
            int i = tid + p * 256;
            int half = i >> 10, rem = i & 1023;
            int row = rem >> 3, cc = rem & 7;
            const __nv_bfloat16* src = (half ? g_Ql : g_Qh)
                + ((size_t)bh * Tt + t0 + row) * HD + cc * 8;
            uint32_t dst = uQ + half * 16384 + row * 128 + (((cc ^ (row & 7))) << 4);
            CPASYNC16(dst, src);
        }
    }
    const __nv_bfloat16* kvsrc[4] = { g_Kh, g_Kl, g_Vh, g_Vl };
#define LOAD_CHUNK(CIDX, ST)                                                   \
    {                                                                          \
        const uint32_t base_ = uS0 + (uint32_t)(ST) * 32768;                   \
        int s0_ = (CIDX) * 64;                                                 \
        _Pragma("unroll")                                                      \
        for (int p = 0; p < 8; ++p) {                                          \
            int i = tid + p * 256;                                             \
            int tile = i >> 9;                                                 \
            int rem = i & 511;                                                 \
            int row = rem >> 3, cc = rem & 7;                                  \
            const __nv_bfloat16* src = kvsrc[tile]                             \
                + ((size_t)bh * Tt + s0_ + row) * HD + cc * 8;                 \
            uint32_t dst = base_ + tile * 8192 + row * 128                     \
                         + (((cc ^ (row & 7))) << 4);                          \
            CPASYNC16(dst, src);                                               \
        }                                                                      \
    }

    LOAD_CHUNK(0, 0);
    asm volatile("cp.async.commit_group;" ::: "memory");
    LOAD_CHUNK(1, 1);
    asm volatile("cp.async.commit_group;" ::: "memory");
    asm volatile("cp.async.wait_group 1;" ::: "memory");
    __syncthreads();

    uint32_t qfh[4][4], qfl[4][4];
    {
        int r = w * 16 + (lane & 15);
        uint32_t rb = uQ + r * 128;
#pragma unroll
        for (int kk = 0; kk < 4; ++kk) {
            uint32_t c = (uint32_t)(2 * kk + (lane >> 4));
            uint32_t off = ((c ^ (r & 7)) << 4);
            LDSM4(qfh[kk], rb + off);
            LDSM4(qfl[kk], rb + 16384 + off);
        }
    }

    float o[8][4];
#pragma unroll
    for (int j = 0; j < 8; ++j)
#pragma unroll
        for (int v = 0; v < 4; ++v) o[j][v] = 0.f;
    float m0r = -1e30f, m1r = -1e30f, l0r = 0.f, l1r = 0.f;

    const int rq = lane >> 2;
    const int cq = (lane & 3) * 2;
    const size_t brow0_base = ((size_t)h * Tt + (t0 + w * 16 + rq)) * Tt;
    const size_t brow1_base = brow0_base + 8 * (size_t)Tt;

    for (int c = 0; c < 16; ++c) {
        if (c == 15) asm volatile("cp.async.wait_group 0;" ::: "memory");
        else         asm volatile("cp.async.wait_group 1;" ::: "memory");
        __syncthreads();

        const uint32_t stb = uS0 + (uint32_t)(c & 1) * 32768;
        const int g = lane >> 3, i = lane & 7;

        float s[8][4];
#pragma unroll
        for (int j = 0; j < 8; ++j)
#pragma unroll
            for (int v = 0; v < 4; ++v) s[j][v] = 0.f;

#pragma unroll
        for (int kk = 0; kk < 4; ++kk) {
            uint32_t kbh[8][2], kbl[8][2];
            const int brow_off = i + ((g >> 1) << 3);
            const int bkc = kk * 2 + (g & 1);
#pragma unroll
            for (int ng = 0; ng < 4; ++ng) {
                int row = ng * 16 + brow_off;
                uint32_t off = (uint32_t)(row * 128 + ((bkc ^ (row & 7)) << 4));
                uint32_t r4[4];
                LDSM4(r4, stb + off);
                kbh[ng * 2][0] = r4[0]; kbh[ng * 2][1] = r4[1];
                kbh[ng * 2 + 1][0] = r4[2]; kbh[ng * 2 + 1][1] = r4[3];
                LDSM4(r4, stb + 8192 + off);
                kbl[ng * 2][0] = r4[0]; kbl[ng * 2][1] = r4[1];
                kbl[ng * 2 + 1][0] = r4[2]; kbl[ng * 2 + 1][1] = r4[3];
            }
#pragma unroll
            for (int nt = 0; nt < 8; ++nt) {
                MMA16816(s[nt], qfh[kk], kbh[nt]);
                MMA16816(s[nt], qfh[kk], kbl[nt]);
                MMA16816(s[nt], qfl[kk], kbh[nt]);
            }
        }

        {
            const float* bp0 = rpb + brow0_base + c * 64 + cq;
            const float* bp1 = rpb + brow1_base + c * 64 + cq;
#pragma unroll
            for (int j = 0; j < 8; ++j) {
                float2 b0 = *reinterpret_cast<const float2*>(bp0 + j * 8);
                float2 b1 = *reinterpret_cast<const float2*>(bp1 + j * 8);
                s[j][0] += b0.x; s[j][1] += b0.y;
                s[j][2] += b1.x; s[j][3] += b1.y;
            }
        }

        float cm0 = -1e30f, cm1 = -1e30f;
#pragma unroll
        for (int j = 0; j < 8; ++j) {
            cm0 = fmaxf(cm0, fmaxf(s[j][0], s[j][1]));
            cm1 = fmaxf(cm1, fmaxf(s[j][2], s[j][3]));
        }
        cm0 = fmaxf(cm0, __shfl_xor_sync(0xffffffffu, cm0, 1));
        cm0 = fmaxf(cm0, __shfl_xor_sync(0xffffffffu, cm0, 2));
        cm1 = fmaxf(cm1, __shfl_xor_sync(0xffffffffu, cm1, 1));
        cm1 = fmaxf(cm1, __shfl_xor_sync(0xffffffffu, cm1, 2));
        float m0n = fmaxf(m0r, cm0), m1n = fmaxf(m1r, cm1);
        float cor0 = __expf(m0r - m0n), cor1 = __expf(m1r - m1n);
        m0r = m0n; m1r = m1n;
        float rs0 = 0.f, rs1 = 0.f;
#pragma unroll
        for (int j = 0; j < 8; ++j) {
            s[j][0] = __expf(s[j][0] - m0n);
            s[j][1] = __expf(s[j][1] - m0n);
            s[j][2] = __expf(s[j][2] - m1n);
            s[j][3] = __expf(s[j][3] - m1n);
            rs0 += s[j][0] + s[j][1];
            rs1 += s[j][2] + s[j][3];
        }
        rs0 += __shfl_xor_sync(0xffffffffu, rs0, 1);
        rs0 += __shfl_xor_sync(0xffffffffu, rs0, 2);
        rs1 += __shfl_xor_sync(0xffffffffu, rs1, 1);
        rs1 += __shfl_xor_sync(0xffffffffu, rs1, 2);
        l0r = l0r * cor0 + rs0;
        l1r = l1r * cor1 + rs1;
#pragma unroll
        for (int j = 0; j < 8; ++j) {
            o[j][0] *= cor0; o[j][1] *= cor0;
            o[j][2] *= cor1; o[j][3] *= cor1;
        }

        uint32_t ph[8][2], pl[8][2];
#pragma unroll
        for (int j = 0; j < 8; ++j) {
            float2 v0 = {s[j][0], s[j][1]};
            __nv_bfloat162 hh0 = __float22bfloat162_rn(v0);
            ph[j][0] = *reinterpret_cast<uint32_t*>(&hh0);
            float2 lo0 = {s[j][0] - __bfloat162float(hh0.x),
                          s[j][1] - __bfloat162float(hh0.y)};
            __nv_bfloat162 ll0 = __float22bfloat162_rn(lo0);
            pl[j][0] = *reinterpret_cast<uint32_t*>(&ll0);
            float2 v1 = {s[j][2], s[j][3]};
            __nv_bfloat162 hh1 = __float22bfloat162_rn(v1);
            ph[j][1] = *reinterpret_cast<uint32_t*>(&hh1);
            float2 lo1 = {s[j][2] - __bfloat162float(hh1.x),
                          s[j][3] - __bfloat162float(hh1.y)};
            __nv_bfloat162 ll1 = __float22bfloat162_rn(lo1);
            pl[j][1] = *reinterpret_cast<uint32_t*>(&ll1);
        }

#pragma unroll
        for (int kk = 0; kk < 4; ++kk) {
            uint32_t a_h[4] = { ph[2*kk][0], ph[2*kk][1], ph[2*kk+1][0], ph[2*kk+1][1] };
            uint32_t a_l[4] = { pl[2*kk][0], pl[2*kk][1], pl[2*kk+1][0], pl[2*kk+1][1] };
            uint32_t vbh[8][2], vbl[8][2];
            const int srow = kk * 16 + i + ((g >> 1) << 3);
#pragma unroll
            for (int dg = 0; dg < 4; ++dg) {
                int ck = dg * 2 + (g & 1);
                uint32_t off = (uint32_t)(srow * 128 + ((ck ^ (srow & 7)) << 4));
                uint32_t r4[4];
                LDSM4T(r4, stb + 16384 + off);
                vbh[dg * 2][0] = r4[0]; vbh[dg * 2][1] = r4[2];
                vbh[dg * 2 + 1][0] = r4[1]; vbh[dg * 2 + 1][1] = r4[3];
                LDSM4T(r4, stb + 24576 + off);
                vbl[dg * 2][0] = r4[0]; vbl[dg * 2][1] = r4[2];
                vbl[dg * 2 + 1][0] = r4[1]; vbl[dg * 2 + 1][1] = r4[3];
            }
#pragma unroll
            for (int dt = 0; dt < 8; ++dt) {
                MMA16816(o[dt], a_h, vbh[dt]);
                MMA16816(o[dt], a_h, vbl[dt]);
                MMA16816(o[dt], a_l, vbh[dt]);
            }
        }

        __syncthreads();
        if (c + 2 < 16) {
            LOAD_CHUNK(c + 2, c & 1);
            asm volatile("cp.async.commit_group;" ::: "memory");
        }
    }

    float inv0 = 1.f / l0r, inv1 = 1.f / l1r;
    int t_row0 = t0 + w * 16 + rq;
    int t_row1 = t_row0 + 8;
#pragma unroll
    for (int j = 0; j < 8; ++j) {
        int d = j * 8 + cq;
        size_t i0 = ((size_t)t_row0 * Bb + b) * Ee + h * HD + d;
        size_t i1 = ((size_t)t_row1 * Bb + b) * Ee + h * HD + d;
        float x0 = o[j][0] * inv0, y0 = o[j][1] * inv0;
        float x1 = o[j][2] * inv1, y1 = o[j][3] * inv1;
        float2 v0 = {x0, y0};
        __nv_bfloat162 hh0 = __float22bfloat162_rn(v0);
        *reinterpret_cast<__nv_bfloat162*>(g_AOh + i0) = hh0;
        float2 lo0 = {x0 - __bfloat162float(hh0.x), y0 - __bfloat162float(hh0.y)};
        *reinterpret_cast<__nv_bfloat162*>(g_AOl + i0) = __float22bfloat162_rn(lo0);
        float2 v1 = {x1, y1};
        __nv_bfloat162 hh1 = __float22bfloat162_rn(v1);
        *reinterpret_cast<__nv_bfloat162*>(g_AOh + i1) = hh1;
        float2 lo1 = {x1 - __bfloat162float(hh1.x), y1 - __bfloat162float(hh1.y)};
        *reinterpret_cast<__nv_bfloat162*>(g_AOl + i1) = __float22bfloat162_rn(lo1);
    }
#undef LOAD_CHUNK
}

// ---------------------------------------------------------------------------
extern "C" void kernel_launch(void* const* d_in, const int* in_sizes, int n_in,
                              void* d_out, int out_size)
{
    const float* query = (const float*)d_in[0];
    const float* ipw   = (const float*)d_in[1];
    const float* ipb   = (const float*)d_in[2];
    const float* il    = (const float*)d_in[3];
    const float* ir    = (const float*)d_in[4];
    const float* opw   = (const float*)d_in[5];
    const float* opb   = (const float*)d_in[6];
    const float* ol    = (const float*)d_in[7];
    const float* orr   = (const float*)d_in[8];
    const float* rpb   = (const float*)d_in[9];
    float* out = (float*)d_out;

    static bool attr_set = false;
    if (!attr_set) {
        cudaFuncSetAttribute(gemm_mma<0>,
            cudaFuncAttributeMaxDynamicSharedMemorySize, 131072);
        cudaFuncSetAttribute(gemm_mma<1>,
            cudaFuncAttributeMaxDynamicSharedMemorySize, 131072);
        cudaFuncSetAttribute(attn_mma,
            cudaFuncAttributeMaxDynamicSharedMemorySize, 98304);
        attr_set = true;
    }

    weff_kernel<0><<<(F3 * Ee + 255) / 256, 256>>>(ipw, il, ir);
    weff_kernel<1><<<(Ee * Ee + 255) / 256, 256>>>(opw, ol, orr);
    qsplit_kernel<<<Nrows * Ee / 1024, 256>>>(query);

    gemm_mma<0><<<dim3(F3 / BN, Nrows / BM), 256, 131072>>>(ipb, nullptr, F3, Ee);

    attn_mma<<<dim3(Bb * Hh, Tt / 128), 256, 98304>>>(rpb);

    gemm_mma<1><<<dim3(Ee / BN, Nrows / BM), 256, 131072>>>(opb, out, Ee, Ee);
}

// round 6
// speedup vs baseline: 4.1501x; 1.0832x over previous
#include <cuda_runtime.h>
#include <cuda_bf16.h>
#include <cstdint>

// ---------------------------------------------------------------------------
// MultiheadAttention with low-rank-augmented in/out projections.
// T=1024, B=8, E=1024, H=16, R=16, HD=64.
//
// R6: GEMMs retiled to 128x64x32 with launch_bounds(256,2) -> 2 CTAs/SM
//     (occupancy was the R5 limiter). 4-stage cp.async, 1 sync/chunk.
//     Attention unchanged from R4/R5.
// ---------------------------------------------------------------------------

namespace {
constexpr int Tt = 1024;
constexpr int Bb = 8;
constexpr int Ee = 1024;
constexpr int Hh = 16;
constexpr int Rr = 16;
constexpr int HD = 64;
constexpr int F3 = 3 * Ee;          // 3072
constexpr int Nrows = Tt * Bb;      // 8192
constexpr int BM = 128, BN = 64, BK = 32;
constexpr int STAGE_B = 24576;      // Ah 8K, Al 8K, Bh 4K, Bl 4K
}

// Scratch (device globals; no runtime allocation).
__device__ __align__(16) __nv_bfloat16 g_Win_h[F3 * Ee];
__device__ __align__(16) __nv_bfloat16 g_Win_l[F3 * Ee];
__device__ __align__(16) __nv_bfloat16 g_Wout_h[Ee * Ee];
__device__ __align__(16) __nv_bfloat16 g_Wout_l[Ee * Ee];
__device__ __align__(16) __nv_bfloat16 g_Ah[Nrows * Ee];
__device__ __align__(16) __nv_bfloat16 g_Al[Nrows * Ee];
__device__ __align__(16) __nv_bfloat16 g_AOh[Nrows * Ee];
__device__ __align__(16) __nv_bfloat16 g_AOl[Nrows * Ee];
__device__ __align__(16) __nv_bfloat16 g_Qh[Bb * Hh * Tt * HD];
__device__ __align__(16) __nv_bfloat16 g_Ql[Bb * Hh * Tt * HD];
__device__ __align__(16) __nv_bfloat16 g_Kh[Bb * Hh * Tt * HD];
__device__ __align__(16) __nv_bfloat16 g_Kl[Bb * Hh * Tt * HD];
__device__ __align__(16) __nv_bfloat16 g_Vh[Bb * Hh * Tt * HD];
__device__ __align__(16) __nv_bfloat16 g_Vl[Bb * Hh * Tt * HD];

// ---------------------------------------------------------------------------
__device__ __forceinline__ uint32_t smem_u32(const void* p) {
    uint32_t a;
    asm("{ .reg .u64 t; cvta.to.shared.u64 t, %1; cvt.u32.u64 %0, t; }"
        : "=r"(a) : "l"(p));
    return a;
}

__device__ __forceinline__ void split_bf(float x, __nv_bfloat16& h, __nv_bfloat16& l) {
    h = __float2bfloat16(x);
    l = __float2bfloat16(x - __bfloat162float(h));
}

#define LDSM4(R, A)                                                           \
    asm volatile("ldmatrix.sync.aligned.m8n8.x4.shared.b16 {%0,%1,%2,%3}, [%4];" \
                 : "=r"((R)[0]), "=r"((R)[1]), "=r"((R)[2]), "=r"((R)[3])     \
                 : "r"(A))

#define LDSM4T(R, A)                                                          \
    asm volatile("ldmatrix.sync.aligned.m8n8.x4.trans.shared.b16 {%0,%1,%2,%3}, [%4];" \
                 : "=r"((R)[0]), "=r"((R)[1]), "=r"((R)[2]), "=r"((R)[3])     \
                 : "r"(A))

#define MMA16816(C, A, B)                                                     \
    asm volatile("mma.sync.aligned.m16n8k16.row.col.f32.bf16.bf16.f32 "       \
                 "{%0,%1,%2,%3}, {%4,%5,%6,%7}, {%8,%9}, {%0,%1,%2,%3};"      \
                 : "+f"((C)[0]), "+f"((C)[1]), "+f"((C)[2]), "+f"((C)[3])     \
                 : "r"((A)[0]), "r"((A)[1]), "r"((A)[2]), "r"((A)[3]),        \
                   "r"((B)[0]), "r"((B)[1]))

#define CPASYNC16(D, S)                                                       \
    asm volatile("cp.async.cg.shared.global [%0], [%1], 16;"                  \
                 :: "r"(D), "l"(S))

// ---------------------------------------------------------------------------
// W_eff = W + L@R, written as bf16 hi/lo split.
// ---------------------------------------------------------------------------
template <int WHICH>
__global__ void weff_kernel(const float* __restrict__ W,
                            const float* __restrict__ L,
                            const float* __restrict__ Rm)
{
    const int F = (WHICH == 0) ? F3 : Ee;
    __nv_bfloat16* oh = (WHICH == 0) ? g_Win_h : g_Wout_h;
    __nv_bfloat16* ol = (WHICH == 0) ? g_Win_l : g_Wout_l;
    int idx = blockIdx.x * 256 + threadIdx.x;
    if (idx >= F * Ee) return;
    int f = idx >> 10;
    int e = idx & 1023;
    float s = W[idx];
#pragma unroll
    for (int r = 0; r < Rr; ++r)
        s = fmaf(L[f * Rr + r], Rm[r * Ee + e], s);
    __nv_bfloat16 h, l;
    split_bf(s, h, l);
    oh[idx] = h;
    ol[idx] = l;
}

// ---------------------------------------------------------------------------
// Split query (fp32) into bf16 hi/lo.
// ---------------------------------------------------------------------------
__global__ void qsplit_kernel(const float* __restrict__ q)
{
    int idx = (blockIdx.x * 256 + threadIdx.x) * 4;
    float4 v = *reinterpret_cast<const float4*>(q + idx);
    __nv_bfloat16 h0, h1, h2, h3, l0, l1, l2, l3;
    split_bf(v.x, h0, l0); split_bf(v.y, h1, l1);
    split_bf(v.z, h2, l2); split_bf(v.w, h3, l3);
    __nv_bfloat162* ph = reinterpret_cast<__nv_bfloat162*>(g_Ah + idx);
    __nv_bfloat162* pl = reinterpret_cast<__nv_bfloat162*>(g_Al + idx);
    ph[0] = __nv_bfloat162(h0, h1); ph[1] = __nv_bfloat162(h2, h3);
    pl[0] = __nv_bfloat162(l0, l1); pl[1] = __nv_bfloat162(l2, l3);
}

// ---------------------------------------------------------------------------
// Tensor-pipe GEMM via mma.sync bf16 split: C = A·W^T + bias.
// Tile 128x64x32, 8 warps (4x2), warp tile 32x32, 4-stage cp.async (96KB),
// launch_bounds(256,2) -> 2 CTAs/SM.
// MODE 0: scatter to Q/K/V bf16 hi/lo (q scaled 0.125)
// MODE 1: out row-major fp32 + bias
// ---------------------------------------------------------------------------
template <int MODE>
__global__ __launch_bounds__(256, 2)
void gemm_mma(const float* __restrict__ bias, float* __restrict__ out,
              int N, int K)
{
    extern __shared__ __align__(16) char sm[];
    const __nv_bfloat16* Agh = (MODE == 0) ? g_Ah : g_AOh;
    const __nv_bfloat16* Agl = (MODE == 0) ? g_Al : g_AOl;
    const __nv_bfloat16* Bgh = (MODE == 0) ? g_Win_h : g_Wout_h;
    const __nv_bfloat16* Bgl = (MODE == 0) ? g_Win_l : g_Wout_l;

    const int tid  = threadIdx.x;
    const int lane = tid & 31;
    const int wid  = tid >> 5;
    const int wm   = wid >> 1;        // 0..3
    const int wn   = wid & 1;         // 0..1
    const int m0 = blockIdx.y * BM;
    const int n0 = blockIdx.x * BN;

    const uint32_t smb = smem_u32(sm);

    float acc[2][4][4];
#pragma unroll
    for (int a = 0; a < 2; ++a)
#pragma unroll
        for (int b = 0; b < 4; ++b)
#pragma unroll
            for (int c = 0; c < 4; ++c) acc[a][b][c] = 0.f;

    const int nchunk = K / BK;

#define ISSUE_STAGE(CIDX)                                                     \
    {                                                                         \
        uint32_t base_ = smb + (uint32_t)((CIDX) & 3) * STAGE_B;              \
        _Pragma("unroll")                                                     \
        for (int p = 0; p < 2; ++p) {                                         \
            int idx = tid + p * 256;                                          \
            int row = idx >> 2, c8 = idx & 3;                                 \
            uint32_t sw = (uint32_t)(row * 64 + ((c8 ^ ((row >> 1) & 3)) << 4)); \
            size_t go = (size_t)(m0 + row) * K + (CIDX) * 32 + c8 * 8;        \
            CPASYNC16(base_ + sw, Agh + go);                                  \
            CPASYNC16(base_ + 8192 + sw, Agl + go);                           \
        }                                                                     \
        {                                                                     \
            int row = tid >> 2, c8 = tid & 3;                                 \
            uint32_t sw = (uint32_t)(row * 64 + ((c8 ^ ((row >> 1) & 3)) << 4)); \
            size_t go = (size_t)(n0 + row) * K + (CIDX) * 32 + c8 * 8;        \
            CPASYNC16(base_ + 16384 + sw, Bgh + go);                          \
            CPASYNC16(base_ + 20480 + sw, Bgl + go);                          \
        }                                                                     \
        asm volatile("cp.async.commit_group;" ::: "memory");                  \
    }

    ISSUE_STAGE(0);
    ISSUE_STAGE(1);
    ISSUE_STAGE(2);

    for (int c = 0; c < nchunk; ++c) {
        asm volatile("cp.async.wait_group 2;" ::: "memory");
        __syncthreads();

        if (c + 3 < nchunk) ISSUE_STAGE(c + 3);

        {
            uint32_t stb = smb + (uint32_t)(c & 3) * STAGE_B;
            const int g = lane >> 3, i = lane & 7;
#pragma unroll
            for (int ks = 0; ks < 2; ++ks) {
                uint32_t ah[2][4], al[2][4];
                const int arow_off = i + ((g & 1) << 3);
                const int akc = ks * 2 + (g >> 1);
#pragma unroll
                for (int mt = 0; mt < 2; ++mt) {
                    int row = wm * 32 + mt * 16 + arow_off;
                    uint32_t off = (uint32_t)(row * 64 + ((akc ^ ((row >> 1) & 3)) << 4));
                    LDSM4(ah[mt], stb + off);
                    LDSM4(al[mt], stb + 8192 + off);
                }
                uint32_t bh[4][2], bl[4][2];
                const int brow_off = i + ((g >> 1) << 3);
                const int bkc = ks * 2 + (g & 1);
#pragma unroll
                for (int np = 0; np < 2; ++np) {
                    int row = wn * 32 + np * 16 + brow_off;
                    uint32_t off = (uint32_t)(row * 64 + ((bkc ^ ((row >> 1) & 3)) << 4));
                    uint32_t r4[4];
                    LDSM4(r4, stb + 16384 + off);
                    bh[np * 2][0] = r4[0]; bh[np * 2][1] = r4[1];
                    bh[np * 2 + 1][0] = r4[2]; bh[np * 2 + 1][1] = r4[3];
                    LDSM4(r4, stb + 20480 + off);
                    bl[np * 2][0] = r4[0]; bl[np * 2][1] = r4[1];
                    bl[np * 2 + 1][0] = r4[2]; bl[np * 2 + 1][1] = r4[3];
                }
#pragma unroll
                for (int mt = 0; mt < 2; ++mt)
#pragma unroll
                    for (int nb = 0; nb < 4; ++nb) {
                        MMA16816(acc[mt][nb], ah[mt], bh[nb]);
                        MMA16816(acc[mt][nb], ah[mt], bl[nb]);
                        MMA16816(acc[mt][nb], al[mt], bh[nb]);
                    }
            }
        }
    }
#undef ISSUE_STAGE

    __syncthreads();   // all LDSM done before epilogue reuses nothing; safety for exit

    const int r = lane >> 2, tg = lane & 3;
#pragma unroll
    for (int mt = 0; mt < 2; ++mt) {
#pragma unroll
        for (int nb = 0; nb < 4; ++nb) {
            int m = m0 + wm * 32 + mt * 16 + r;
            int n = n0 + wn * 32 + nb * 8 + tg * 2;
            float2 bb = *reinterpret_cast<const float2*>(bias + n);
#pragma unroll
            for (int half = 0; half < 2; ++half) {
                int mm = m + half * 8;
                float v0 = acc[mt][nb][half * 2 + 0] + bb.x;
                float v1 = acc[mt][nb][half * 2 + 1] + bb.y;
                if (MODE == 1) {
                    float2 vv = {v0, v1};
                    *reinterpret_cast<float2*>(out + (size_t)mm * N + n) = vv;
                } else {
                    int t = mm >> 3;
                    int b = mm & 7;
                    int which = n >> 10;
                    int h = (n >> 6) & 15;
                    int d = n & 63;
                    float sc = (which == 0) ? 0.125f : 1.0f;
                    float x = v0 * sc, y = v1 * sc;
                    __nv_bfloat16* bph = (which == 0) ? g_Qh : (which == 1) ? g_Kh : g_Vh;
                    __nv_bfloat16* bpl = (which == 0) ? g_Ql : (which == 1) ? g_Kl : g_Vl;
                    size_t off = ((size_t)(b * Hh + h) * Tt + t) * HD + d;
                    float2 vv = {x, y};
                    __nv_bfloat162 hh = __float22bfloat162_rn(vv);
                    *reinterpret_cast<__nv_bfloat162*>(bph + off) = hh;
                    float2 lo = {x - __bfloat162float(hh.x), y - __bfloat162float(hh.y)};
                    *reinterpret_cast<__nv_bfloat162*>(bpl + off) = __float22bfloat162_rn(lo);
                }
            }
        }
    }
}

// ---------------------------------------------------------------------------
// Flash attention on tensor pipe (unchanged from R5).
// ---------------------------------------------------------------------------
__global__ __launch_bounds__(256, 1)
void attn_mma(const float* __restrict__ rpb)
{
    extern __shared__ __align__(16) char sm[];
    const int tid = threadIdx.x;
    const int lane = tid & 31;
    const int w = tid >> 5;
    const int bh = blockIdx.x;
    const int h = bh & 15, b = bh >> 4;
    const int t0 = blockIdx.y * 128;

    const uint32_t uQ = smem_u32(sm);
    const uint32_t uS0 = uQ + 32768;

    {
#pragma unroll
        for (int p = 0; p < 8; ++p) {
            int i = tid + p * 256;
            int half = i >> 10, rem = i & 1023;
            int row = rem >> 3, cc = rem & 7;
            const __nv_bfloat16* src = (half ? g_Ql : g_Qh)
                + ((size_t)bh * Tt + t0 + row) * HD + cc * 8;
            uint32_t dst = uQ + half * 16384 + row * 128 + (((cc ^ (row & 7))) << 4);
            CPASYNC16(dst, src);
        }
    }
    const __nv_bfloat16* kvsrc[4] = { g_Kh, g_Kl, g_Vh, g_Vl };
#define LOAD_CHUNK(CIDX, ST)                                                   \
    {                                                                          \
        const uint32_t base_ = uS0 + (uint32_t)(ST) * 32768;                   \
        int s0_ = (CIDX) * 64;                                                 \
        _Pragma("unroll")                                                      \
        for (int p = 0; p < 8; ++p) {                                          \
            int i = tid + p * 256;                                             \
            int tile = i >> 9;                                                 \
            int rem = i & 511;                                                 \
            int row = rem >> 3, cc = rem & 7;                                  \
            const __nv_bfloat16* src = kvsrc[tile]                             \
                + ((size_t)bh * Tt + s0_ + row) * HD + cc * 8;                 \
            uint32_t dst = base_ + tile * 8192 + row * 128                     \
                         + (((cc ^ (row & 7))) << 4);                          \
            CPASYNC16(dst, src);                                               \
        }                                                                      \
    }

    LOAD_CHUNK(0, 0);
    asm volatile("cp.async.commit_group;" ::: "memory");
    LOAD_CHUNK(1, 1);
    asm volatile("cp.async.commit_group;" ::: "memory");
    asm volatile("cp.async.wait_group 1;" ::: "memory");
    __syncthreads();

    uint32_t qfh[4][4], qfl[4][4];
    {
        int r = w * 16 + (lane & 15);
        uint32_t rb = uQ + r * 128;
#pragma unroll
        for (int kk = 0; kk < 4; ++kk) {
            uint32_t c = (uint32_t)(2 * kk + (lane >> 4));
            uint32_t off = ((c ^ (r & 7)) << 4);
            LDSM4(qfh[kk], rb + off);
            LDSM4(qfl[kk], rb + 16384 + off);
        }
    }

    float o[8][4];
#pragma unroll
    for (int j = 0; j < 8; ++j)
#pragma unroll
        for (int v = 0; v < 4; ++v) o[j][v] = 0.f;
    float m0r = -1e30f, m1r = -1e30f, l0r = 0.f, l1r = 0.f;

    const int rq = lane >> 2;
    const int cq = (lane & 3) * 2;
    const size_t brow0_base = ((size_t)h * Tt + (t0 + w * 16 + rq)) * Tt;
    const size_t brow1_base = brow0_base + 8 * (size_t)Tt;

    for (int c = 0; c < 16; ++c) {
        if (c == 15) asm volatile("cp.async.wait_group 0;" ::: "memory");
        else         asm volatile("cp.async.wait_group 1;" ::: "memory");
        __syncthreads();

        const uint32_t stb = uS0 + (uint32_t)(c & 1) * 32768;
        const int g = lane >> 3, i = lane & 7;

        float s[8][4];
#pragma unroll
        for (int j = 0; j < 8; ++j)
#pragma unroll
            for (int v = 0; v < 4; ++v) s[j][v] = 0.f;

#pragma unroll
        for (int kk = 0; kk < 4; ++kk) {
            uint32_t kbh[8][2], kbl[8][2];
            const int brow_off = i + ((g >> 1) << 3);
            const int bkc = kk * 2 + (g & 1);
#pragma unroll
            for (int ng = 0; ng < 4; ++ng) {
                int row = ng * 16 + brow_off;
                uint32_t off = (uint32_t)(row * 128 + ((bkc ^ (row & 7)) << 4));
                uint32_t r4[4];
                LDSM4(r4, stb + off);
                kbh[ng * 2][0] = r4[0]; kbh[ng * 2][1] = r4[1];
                kbh[ng * 2 + 1][0] = r4[2]; kbh[ng * 2 + 1][1] = r4[3];
                LDSM4(r4, stb + 8192 + off);
                kbl[ng * 2][0] = r4[0]; kbl[ng * 2][1] = r4[1];
                kbl[ng * 2 + 1][0] = r4[2]; kbl[ng * 2 + 1][1] = r4[3];
            }
#pragma unroll
            for (int nt = 0; nt < 8; ++nt) {
                MMA16816(s[nt], qfh[kk], kbh[nt]);
                MMA16816(s[nt], qfh[kk], kbl[nt]);
                MMA16816(s[nt], qfl[kk], kbh[nt]);
            }
        }

        {
            const float* bp0 = rpb + brow0_base + c * 64 + cq;
            const float* bp1 = rpb + brow1_base + c * 64 + cq;
#pragma unroll
            for (int j = 0; j < 8; ++j) {
                float2 b0 = *reinterpret_cast<const float2*>(bp0 + j * 8);
                float2 b1 = *reinterpret_cast<const float2*>(bp1 + j * 8);
                s[j][0] += b0.x; s[j][1] += b0.y;
                s[j][2] += b1.x; s[j][3] += b1.y;
            }
        }

        float cm0 = -1e30f, cm1 = -1e30f;
#pragma unroll
        for (int j = 0; j < 8; ++j) {
            cm0 = fmaxf(cm0, fmaxf(s[j][0], s[j][1]));
            cm1 = fmaxf(cm1, fmaxf(s[j][2], s[j][3]));
        }
        cm0 = fmaxf(cm0, __shfl_xor_sync(0xffffffffu, cm0, 1));
        cm0 = fmaxf(cm0, __shfl_xor_sync(0xffffffffu, cm0, 2));
        cm1 = fmaxf(cm1, __shfl_xor_sync(0xffffffffu, cm1, 1));
        cm1 = fmaxf(cm1, __shfl_xor_sync(0xffffffffu, cm1, 2));
        float m0n = fmaxf(m0r, cm0), m1n = fmaxf(m1r, cm1);
        float cor0 = __expf(m0r - m0n), cor1 = __expf(m1r - m1n);
        m0r = m0n; m1r = m1n;
        float rs0 = 0.f, rs1 = 0.f;
#pragma unroll
        for (int j = 0; j < 8; ++j) {
            s[j][0] = __expf(s[j][0] - m0n);
            s[j][1] = __expf(s[j][1] - m0n);
            s[j][2] = __expf(s[j][2] - m1n);
            s[j][3] = __expf(s[j][3] - m1n);
            rs0 += s[j][0] + s[j][1];
            rs1 += s[j][2] + s[j][3];
        }
        rs0 += __shfl_xor_sync(0xffffffffu, rs0, 1);
        rs0 += __shfl_xor_sync(0xffffffffu, rs0, 2);
        rs1 += __shfl_xor_sync(0xffffffffu, rs1, 1);
        rs1 += __shfl_xor_sync(0xffffffffu, rs1, 2);
        l0r = l0r * cor0 + rs0;
        l1r = l1r * cor1 + rs1;
#pragma unroll
        for (int j = 0; j < 8; ++j) {
            o[j][0] *= cor0; o[j][1] *= cor0;
            o[j][2] *= cor1; o[j][3] *= cor1;
        }

        uint32_t ph[8][2], pl[8][2];
#pragma unroll
        for (int j = 0; j < 8; ++j) {
            float2 v0 = {s[j][0], s[j][1]};
            __nv_bfloat162 hh0 = __float22bfloat162_rn(v0);
            ph[j][0] = *reinterpret_cast<uint32_t*>(&hh0);
            float2 lo0 = {s[j][0] - __bfloat162float(hh0.x),
                          s[j][1] - __bfloat162float(hh0.y)};
            __nv_bfloat162 ll0 = __float22bfloat162_rn(lo0);
            pl[j][0] = *reinterpret_cast<uint32_t*>(&ll0);
            float2 v1 = {s[j][2], s[j][3]};
            __nv_bfloat162 hh1 = __float22bfloat162_rn(v1);
            ph[j][1] = *reinterpret_cast<uint32_t*>(&hh1);
            float2 lo1 = {s[j][2] - __bfloat162float(hh1.x),
                          s[j][3] - __bfloat162float(hh1.y)};
            __nv_bfloat162 ll1 = __float22bfloat162_rn(lo1);
            pl[j][1] = *reinterpret_cast<uint32_t*>(&ll1);
        }

#pragma unroll
        for (int kk = 0; kk < 4; ++kk) {
            uint32_t a_h[4] = { ph[2*kk][0], ph[2*kk][1], ph[2*kk+1][0], ph[2*kk+1][1] };
            uint32_t a_l[4] = { pl[2*kk][0], pl[2*kk][1], pl[2*kk+1][0], pl[2*kk+1][1] };
            uint32_t vbh[8][2], vbl[8][2];
            const int srow = kk * 16 + i + ((g >> 1) << 3);
#pragma unroll
            for (int dg = 0; dg < 4; ++dg) {
                int ck = dg * 2 + (g & 1);
                uint32_t off = (uint32_t)(srow * 128 + ((ck ^ (srow & 7)) << 4));
                uint32_t r4[4];
                LDSM4T(r4, stb + 16384 + off);
                vbh[dg * 2][0] = r4[0]; vbh[dg * 2][1] = r4[2];
                vbh[dg * 2 + 1][0] = r4[1]; vbh[dg * 2 + 1][1] = r4[3];
                LDSM4T(r4, stb + 24576 + off);
                vbl[dg * 2][0] = r4[0]; vbl[dg * 2][1] = r4[2];
                vbl[dg * 2 + 1][0] = r4[1]; vbl[dg * 2 + 1][1] = r4[3];
            }
#pragma unroll
            for (int dt = 0; dt < 8; ++dt) {
                MMA16816(o[dt], a_h, vbh[dt]);
                MMA16816(o[dt], a_h, vbl[dt]);
                MMA16816(o[dt], a_l, vbh[dt]);
            }
        }

        __syncthreads();
        if (c + 2 < 16) {
            LOAD_CHUNK(c + 2, c & 1);
            asm volatile("cp.async.commit_group;" ::: "memory");
        }
    }

    float inv0 = 1.f / l0r, inv1 = 1.f / l1r;
    int t_row0 = t0 + w * 16 + rq;
    int t_row1 = t_row0 + 8;
#pragma unroll
    for (int j = 0; j < 8; ++j) {
        int d = j * 8 + cq;
        size_t i0 = ((size_t)t_row0 * Bb + b) * Ee + h * HD + d;
        size_t i1 = ((size_t)t_row1 * Bb + b) * Ee + h * HD + d;
        float x0 = o[j][0] * inv0, y0 = o[j][1] * inv0;
        float x1 = o[j][2] * inv1, y1 = o[j][3] * inv1;
        float2 v0 = {x0, y0};
        __nv_bfloat162 hh0 = __float22bfloat162_rn(v0);
        *reinterpret_cast<__nv_bfloat162*>(g_AOh + i0) = hh0;
        float2 lo0 = {x0 - __bfloat162float(hh0.x), y0 - __bfloat162float(hh0.y)};
        *reinterpret_cast<__nv_bfloat162*>(g_AOl + i0) = __float22bfloat162_rn(lo0);
        float2 v1 = {x1, y1};
        __nv_bfloat162 hh1 = __float22bfloat162_rn(v1);
        *reinterpret_cast<__nv_bfloat162*>(g_AOh + i1) = hh1;
        float2 lo1 = {x1 - __bfloat162float(hh1.x), y1 - __bfloat162float(hh1.y)};
        *reinterpret_cast<__nv_bfloat162*>(g_AOl + i1) = __float22bfloat162_rn(lo1);
    }
#undef LOAD_CHUNK
}

// ---------------------------------------------------------------------------
extern "C" void kernel_launch(void* const* d_in, const int* in_sizes, int n_in,
                              void* d_out, int out_size)
{
    const float* query = (const float*)d_in[0];
    const float* ipw   = (const float*)d_in[1];
    const float* ipb   = (const float*)d_in[2];
    const float* il    = (const float*)d_in[3];
    const float* ir    = (const float*)d_in[4];
    const float* opw   = (const float*)d_in[5];
    const float* opb   = (const float*)d_in[6];
    const float* ol    = (const float*)d_in[7];
    const float* orr   = (const float*)d_in[8];
    const float* rpb   = (const float*)d_in[9];
    float* out = (float*)d_out;

    static bool attr_set = false;
    if (!attr_set) {
        cudaFuncSetAttribute(gemm_mma<0>,
            cudaFuncAttributeMaxDynamicSharedMemorySize, 98304);
        cudaFuncSetAttribute(gemm_mma<1>,
            cudaFuncAttributeMaxDynamicSharedMemorySize, 98304);
        cudaFuncSetAttribute(attn_mma,
            cudaFuncAttributeMaxDynamicSharedMemorySize, 98304);
        attr_set = true;
    }

    weff_kernel<0><<<(F3 * Ee + 255) / 256, 256>>>(ipw, il, ir);
    weff_kernel<1><<<(Ee * Ee + 255) / 256, 256>>>(opw, ol, orr);
    qsplit_kernel<<<Nrows * Ee / 1024, 256>>>(query);

    gemm_mma<0><<<dim3(F3 / BN, Nrows / BM), 256, 98304>>>(ipb, nullptr, F3, Ee);

    attn_mma<<<dim3(Bb * Hh, Tt / 128), 256, 98304>>>(rpb);

    gemm_mma<1><<<dim3(Ee / BN, Nrows / BM), 256, 98304>>>(opb, out, Ee, Ee);
}

// round 7
// speedup vs baseline: 4.4812x; 1.0798x over previous
#include <cuda_runtime.h>
#include <cuda_bf16.h>
#include <cstdint>

// ---------------------------------------------------------------------------
// MultiheadAttention with low-rank-augmented in/out projections.
// T=1024, B=8, E=1024, H=16, R=16, HD=64.
//
// R7: attention to 2 CTAs/SM (launch_bounds(256,2)); Q fragments re-loaded
//     from smem per k-step instead of held in registers (reg diet to <=128).
//     GEMMs unchanged from R6.
// ---------------------------------------------------------------------------

namespace {
constexpr int Tt = 1024;
constexpr int Bb = 8;
constexpr int Ee = 1024;
constexpr int Hh = 16;
constexpr int Rr = 16;
constexpr int HD = 64;
constexpr int F3 = 3 * Ee;          // 3072
constexpr int Nrows = Tt * Bb;      // 8192
constexpr int BM = 128, BN = 64, BK = 32;
constexpr int STAGE_B = 24576;      // Ah 8K, Al 8K, Bh 4K, Bl 4K
}

// Scratch (device globals; no runtime allocation).
__device__ __align__(16) __nv_bfloat16 g_Win_h[F3 * Ee];
__device__ __align__(16) __nv_bfloat16 g_Win_l[F3 * Ee];
__device__ __align__(16) __nv_bfloat16 g_Wout_h[Ee * Ee];
__device__ __align__(16) __nv_bfloat16 g_Wout_l[Ee * Ee];
__device__ __align__(16) __nv_bfloat16 g_Ah[Nrows * Ee];
__device__ __align__(16) __nv_bfloat16 g_Al[Nrows * Ee];
__device__ __align__(16) __nv_bfloat16 g_AOh[Nrows * Ee];
__device__ __align__(16) __nv_bfloat16 g_AOl[Nrows * Ee];
__device__ __align__(16) __nv_bfloat16 g_Qh[Bb * Hh * Tt * HD];
__device__ __align__(16) __nv_bfloat16 g_Ql[Bb * Hh * Tt * HD];
__device__ __align__(16) __nv_bfloat16 g_Kh[Bb * Hh * Tt * HD];
__device__ __align__(16) __nv_bfloat16 g_Kl[Bb * Hh * Tt * HD];
__device__ __align__(16) __nv_bfloat16 g_Vh[Bb * Hh * Tt * HD];
__device__ __align__(16) __nv_bfloat16 g_Vl[Bb * Hh * Tt * HD];

// ---------------------------------------------------------------------------
__device__ __forceinline__ uint32_t smem_u32(const void* p) {
    uint32_t a;
    asm("{ .reg .u64 t; cvta.to.shared.u64 t, %1; cvt.u32.u64 %0, t; }"
        : "=r"(a) : "l"(p));
    return a;
}

__device__ __forceinline__ void split_bf(float x, __nv_bfloat16& h, __nv_bfloat16& l) {
    h = __float2bfloat16(x);
    l = __float2bfloat16(x - __bfloat162float(h));
}

#define LDSM4(R, A)                                                           \
    asm volatile("ldmatrix.sync.aligned.m8n8.x4.shared.b16 {%0,%1,%2,%3}, [%4];" \
                 : "=r"((R)[0]), "=r"((R)[1]), "=r"((R)[2]), "=r"((R)[3])     \
                 : "r"(A))

#define LDSM4T(R, A)                                                          \
    asm volatile("ldmatrix.sync.aligned.m8n8.x4.trans.shared.b16 {%0,%1,%2,%3}, [%4];" \
                 : "=r"((R)[0]), "=r"((R)[1]), "=r"((R)[2]), "=r"((R)[3])     \
                 : "r"(A))

#define MMA16816(C, A, B)                                                     \
    asm volatile("mma.sync.aligned.m16n8k16.row.col.f32.bf16.bf16.f32 "       \
                 "{%0,%1,%2,%3}, {%4,%5,%6,%7}, {%8,%9}, {%0,%1,%2,%3};"      \
                 : "+f"((C)[0]), "+f"((C)[1]), "+f"((C)[2]), "+f"((C)[3])     \
                 : "r"((A)[0]), "r"((A)[1]), "r"((A)[2]), "r"((A)[3]),        \
                   "r"((B)[0]), "r"((B)[1]))

#define CPASYNC16(D, S)                                                       \
    asm volatile("cp.async.cg.shared.global [%0], [%1], 16;"                  \
                 :: "r"(D), "l"(S))

// ---------------------------------------------------------------------------
// W_eff = W + L@R, written as bf16 hi/lo split.
// ---------------------------------------------------------------------------
template <int WHICH>
__global__ void weff_kernel(const float* __restrict__ W,
                            const float* __restrict__ L,
                            const float* __restrict__ Rm)
{
    const int F = (WHICH == 0) ? F3 : Ee;
    __nv_bfloat16* oh = (WHICH == 0) ? g_Win_h : g_Wout_h;
    __nv_bfloat16* ol = (WHICH == 0) ? g_Win_l : g_Wout_l;
    int idx = blockIdx.x * 256 + threadIdx.x;
    if (idx >= F * Ee) return;
    int f = idx >> 10;
    int e = idx & 1023;
    float s = W[idx];
#pragma unroll
    for (int r = 0; r < Rr; ++r)
        s = fmaf(L[f * Rr + r], Rm[r * Ee + e], s);
    __nv_bfloat16 h, l;
    split_bf(s, h, l);
    oh[idx] = h;
    ol[idx] = l;
}

// ---------------------------------------------------------------------------
// Split query (fp32) into bf16 hi/lo.
// ---------------------------------------------------------------------------
__global__ void qsplit_kernel(const float* __restrict__ q)
{
    int idx = (blockIdx.x * 256 + threadIdx.x) * 4;
    float4 v = *reinterpret_cast<const float4*>(q + idx);
    __nv_bfloat16 h0, h1, h2, h3, l0, l1, l2, l3;
    split_bf(v.x, h0, l0); split_bf(v.y, h1, l1);
    split_bf(v.z, h2, l2); split_bf(v.w, h3, l3);
    __nv_bfloat162* ph = reinterpret_cast<__nv_bfloat162*>(g_Ah + idx);
    __nv_bfloat162* pl = reinterpret_cast<__nv_bfloat162*>(g_Al + idx);
    ph[0] = __nv_bfloat162(h0, h1); ph[1] = __nv_bfloat162(h2, h3);
    pl[0] = __nv_bfloat162(l0, l1); pl[1] = __nv_bfloat162(l2, l3);
}

// ---------------------------------------------------------------------------
// Tensor-pipe GEMM via mma.sync bf16 split: C = A·W^T + bias.
// Tile 128x64x32, 8 warps (4x2), warp tile 32x32, 4-stage cp.async (96KB),
// launch_bounds(256,2) -> 2 CTAs/SM. (unchanged from R6)
// ---------------------------------------------------------------------------
template <int MODE>
__global__ __launch_bounds__(256, 2)
void gemm_mma(const float* __restrict__ bias, float* __restrict__ out,
              int N, int K)
{
    extern __shared__ __align__(16) char sm[];
    const __nv_bfloat16* Agh = (MODE == 0) ? g_Ah : g_AOh;
    const __nv_bfloat16* Agl = (MODE == 0) ? g_Al : g_AOl;
    const __nv_bfloat16* Bgh = (MODE == 0) ? g_Win_h : g_Wout_h;
    const __nv_bfloat16* Bgl = (MODE == 0) ? g_Win_l : g_Wout_l;

    const int tid  = threadIdx.x;
    const int lane = tid & 31;
    const int wid  = tid >> 5;
    const int wm   = wid >> 1;
    const int wn   = wid & 1;
    const int m0 = blockIdx.y * BM;
    const int n0 = blockIdx.x * BN;

    const uint32_t smb = smem_u32(sm);

    float acc[2][4][4];
#pragma unroll
    for (int a = 0; a < 2; ++a)
#pragma unroll
        for (int b = 0; b < 4; ++b)
#pragma unroll
            for (int c = 0; c < 4; ++c) acc[a][b][c] = 0.f;

    const int nchunk = K / BK;

#define ISSUE_STAGE(CIDX)                                                     \
    {                                                                         \
        uint32_t base_ = smb + (uint32_t)((CIDX) & 3) * STAGE_B;              \
        _Pragma("unroll")                                                     \
        for (int p = 0; p < 2; ++p) {                                         \
            int idx = tid + p * 256;                                          \
            int row = idx >> 2, c8 = idx & 3;                                 \
            uint32_t sw = (uint32_t)(row * 64 + ((c8 ^ ((row >> 1) & 3)) << 4)); \
            size_t go = (size_t)(m0 + row) * K + (CIDX) * 32 + c8 * 8;        \
            CPASYNC16(base_ + sw, Agh + go);                                  \
            CPASYNC16(base_ + 8192 + sw, Agl + go);                           \
        }                                                                     \
        {                                                                     \
            int row = tid >> 2, c8 = tid & 3;                                 \
            uint32_t sw = (uint32_t)(row * 64 + ((c8 ^ ((row >> 1) & 3)) << 4)); \
            size_t go = (size_t)(n0 + row) * K + (CIDX) * 32 + c8 * 8;        \
            CPASYNC16(base_ + 16384 + sw, Bgh + go);                          \
            CPASYNC16(base_ + 20480 + sw, Bgl + go);                          \
        }                                                                     \
        asm volatile("cp.async.commit_group;" ::: "memory");                  \
    }

    ISSUE_STAGE(0);
    ISSUE_STAGE(1);
    ISSUE_STAGE(2);

    for (int c = 0; c < nchunk; ++c) {
        asm volatile("cp.async.wait_group 2;" ::: "memory");
        __syncthreads();

        if (c + 3 < nchunk) ISSUE_STAGE(c + 3);

        {
            uint32_t stb = smb + (uint32_t)(c & 3) * STAGE_B;
            const int g = lane >> 3, i = lane & 7;
#pragma unroll
            for (int ks = 0; ks < 2; ++ks) {
                uint32_t ah[2][4], al[2][4];
                const int arow_off = i + ((g & 1) << 3);
                const int akc = ks * 2 + (g >> 1);
#pragma unroll
                for (int mt = 0; mt < 2; ++mt) {
                    int row = wm * 32 + mt * 16 + arow_off;
                    uint32_t off = (uint32_t)(row * 64 + ((akc ^ ((row >> 1) & 3)) << 4));
                    LDSM4(ah[mt], stb + off);
                    LDSM4(al[mt], stb + 8192 + off);
                }
                uint32_t bh[4][2], bl[4][2];
                const int brow_off = i + ((g >> 1) << 3);
                const int bkc = ks * 2 + (g & 1);
#pragma unroll
                for (int np = 0; np < 2; ++np) {
                    int row = wn * 32 + np * 16 + brow_off;
                    uint32_t off = (uint32_t)(row * 64 + ((bkc ^ ((row >> 1) & 3)) << 4));
                    uint32_t r4[4];
                    LDSM4(r4, stb + 16384 + off);
                    bh[np * 2][0] = r4[0]; bh[np * 2][1] = r4[1];
                    bh[np * 2 + 1][0] = r4[2]; bh[np * 2 + 1][1] = r4[3];
                    LDSM4(r4, stb + 20480 + off);
                    bl[np * 2][0] = r4[0]; bl[np * 2][1] = r4[1];
                    bl[np * 2 + 1][0] = r4[2]; bl[np * 2 + 1][1] = r4[3];
                }
#pragma unroll
                for (int mt = 0; mt < 2; ++mt)
#pragma unroll
                    for (int nb = 0; nb < 4; ++nb) {
                        MMA16816(acc[mt][nb], ah[mt], bh[nb]);
                        MMA16816(acc[mt][nb], ah[mt], bl[nb]);
                        MMA16816(acc[mt][nb], al[mt], bh[nb]);
                    }
            }
        }
    }
#undef ISSUE_STAGE

    __syncthreads();

    const int r = lane >> 2, tg = lane & 3;
#pragma unroll
    for (int mt = 0; mt < 2; ++mt) {
#pragma unroll
        for (int nb = 0; nb < 4; ++nb) {
            int m = m0 + wm * 32 + mt * 16 + r;
            int n = n0 + wn * 32 + nb * 8 + tg * 2;
            float2 bb = *reinterpret_cast<const float2*>(bias + n);
#pragma unroll
            for (int half = 0; half < 2; ++half) {
                int mm = m + half * 8;
                float v0 = acc[mt][nb][half * 2 + 0] + bb.x;
                float v1 = acc[mt][nb][half * 2 + 1] + bb.y;
                if (MODE == 1) {
                    float2 vv = {v0, v1};
                    *reinterpret_cast<float2*>(out + (size_t)mm * N + n) = vv;
                } else {
                    int t = mm >> 3;
                    int b = mm & 7;
                    int which = n >> 10;
                    int h = (n >> 6) & 15;
                    int d = n & 63;
                    float sc = (which == 0) ? 0.125f : 1.0f;
                    float x = v0 * sc, y = v1 * sc;
                    __nv_bfloat16* bph = (which == 0) ? g_Qh : (which == 1) ? g_Kh : g_Vh;
                    __nv_bfloat16* bpl = (which == 0) ? g_Ql : (which == 1) ? g_Kl : g_Vl;
                    size_t off = ((size_t)(b * Hh + h) * Tt + t) * HD + d;
                    float2 vv = {x, y};
                    __nv_bfloat162 hh = __float22bfloat162_rn(vv);
                    *reinterpret_cast<__nv_bfloat162*>(bph + off) = hh;
                    float2 lo = {x - __bfloat162float(hh.x), y - __bfloat162float(hh.y)};
                    *reinterpret_cast<__nv_bfloat162*>(bpl + off) = __float22bfloat162_rn(lo);
                }
            }
        }
    }
}

// ---------------------------------------------------------------------------
// Flash attention on tensor pipe. R7: 2 CTAs/SM; Q fragments re-loaded from
// smem per k-step (no persistent Q registers).
// ---------------------------------------------------------------------------
__global__ __launch_bounds__(256, 2)
void attn_mma(const float* __restrict__ rpb)
{
    extern __shared__ __align__(16) char sm[];
    const int tid = threadIdx.x;
    const int lane = tid & 31;
    const int w = tid >> 5;
    const int bh = blockIdx.x;
    const int h = bh & 15, b = bh >> 4;
    const int t0 = blockIdx.y * 128;

    const uint32_t uQ = smem_u32(sm);
    const uint32_t uS0 = uQ + 32768;

    {
#pragma unroll
        for (int p = 0; p < 8; ++p) {
            int i = tid + p * 256;
            int half = i >> 10, rem = i & 1023;
            int row = rem >> 3, cc = rem & 7;
            const __nv_bfloat16* src = (half ? g_Ql : g_Qh)
                + ((size_t)bh * Tt + t0 + row) * HD + cc * 8;
            uint32_t dst = uQ + half * 16384 + row * 128 + (((cc ^ (row & 7))) << 4);
            CPASYNC16(dst, src);
        }
    }
    const __nv_bfloat16* kvsrc[4] = { g_Kh, g_Kl, g_Vh, g_Vl };
#define LOAD_CHUNK(CIDX, ST)                                                   \
    {                                                                          \
        const uint32_t base_ = uS0 + (uint32_t)(ST) * 32768;                   \
        int s0_ = (CIDX) * 64;                                                 \
        _Pragma("unroll")                                                      \
        for (int p = 0; p < 8; ++p) {                                          \
            int i = tid + p * 256;                                             \
            int tile = i >> 9;                                                 \
            int rem = i & 511;                                                 \
            int row = rem >> 3, cc = rem & 7;                                  \
            const __nv_bfloat16* src = kvsrc[tile]                             \
                + ((size_t)bh * Tt + s0_ + row) * HD + cc * 8;                 \
            uint32_t dst = base_ + tile * 8192 + row * 128                     \
                         + (((cc ^ (row & 7))) << 4);                          \
            CPASYNC16(dst, src);                                               \
        }                                                                      \
    }

    LOAD_CHUNK(0, 0);
    asm volatile("cp.async.commit_group;" ::: "memory");
    LOAD_CHUNK(1, 1);
    asm volatile("cp.async.commit_group;" ::: "memory");

    float o[8][4];
#pragma unroll
    for (int j = 0; j < 8; ++j)
#pragma unroll
        for (int v = 0; v < 4; ++v) o[j][v] = 0.f;
    float m0r = -1e30f, m1r = -1e30f, l0r = 0.f, l1r = 0.f;

    const int rq = lane >> 2;
    const int cq = (lane & 3) * 2;
    const size_t brow0_base = ((size_t)h * Tt + (t0 + w * 16 + rq)) * Tt;
    const size_t brow1_base = brow0_base + 8 * (size_t)Tt;

    // Q fragment smem geometry (reloaded per k-step)
    const int qrow = w * 16 + (lane & 15);
    const uint32_t qrb = uQ + qrow * 128;
    const uint32_t qsel = (uint32_t)(lane >> 4);

    for (int c = 0; c < 16; ++c) {
        if (c == 15) asm volatile("cp.async.wait_group 0;" ::: "memory");
        else         asm volatile("cp.async.wait_group 1;" ::: "memory");
        __syncthreads();

        const uint32_t stb = uS0 + (uint32_t)(c & 1) * 32768;
        const int g = lane >> 3, i = lane & 7;

        float s[8][4];
#pragma unroll
        for (int j = 0; j < 8; ++j)
#pragma unroll
            for (int v = 0; v < 4; ++v) s[j][v] = 0.f;

#pragma unroll
        for (int kk = 0; kk < 4; ++kk) {
            // Q fragments for this k-step (hi/lo) from smem
            uint32_t qh[4], ql[4];
            {
                uint32_t ccol = 2u * kk + qsel;
                uint32_t off = ((ccol ^ (qrow & 7)) << 4);
                LDSM4(qh, qrb + off);
                LDSM4(ql, qrb + 16384 + off);
            }
            uint32_t kbh[8][2], kbl[8][2];
            const int brow_off = i + ((g >> 1) << 3);
            const int bkc = kk * 2 + (g & 1);
#pragma unroll
            for (int ng = 0; ng < 4; ++ng) {
                int row = ng * 16 + brow_off;
                uint32_t off = (uint32_t)(row * 128 + ((bkc ^ (row & 7)) << 4));
                uint32_t r4[4];
                LDSM4(r4, stb + off);
                kbh[ng * 2][0] = r4[0]; kbh[ng * 2][1] = r4[1];
                kbh[ng * 2 + 1][0] = r4[2]; kbh[ng * 2 + 1][1] = r4[3];
                LDSM4(r4, stb + 8192 + off);
                kbl[ng * 2][0] = r4[0]; kbl[ng * 2][1] = r4[1];
                kbl[ng * 2 + 1][0] = r4[2]; kbl[ng * 2 + 1][1] = r4[3];
            }
#pragma unroll
            for (int nt = 0; nt < 8; ++nt) {
                MMA16816(s[nt], qh, kbh[nt]);
                MMA16816(s[nt], qh, kbl[nt]);
                MMA16816(s[nt], ql, kbh[nt]);
            }
        }

        {
            const float* bp0 = rpb + brow0_base + c * 64 + cq;
            const float* bp1 = rpb + brow1_base + c * 64 + cq;
#pragma unroll
            for (int j = 0; j < 8; ++j) {
                float2 b0 = *reinterpret_cast<const float2*>(bp0 + j * 8);
                float2 b1 = *reinterpret_cast<const float2*>(bp1 + j * 8);
                s[j][0] += b0.x; s[j][1] += b0.y;
                s[j][2] += b1.x; s[j][3] += b1.y;
            }
        }

        float cm0 = -1e30f, cm1 = -1e30f;
#pragma unroll
        for (int j = 0; j < 8; ++j) {
            cm0 = fmaxf(cm0, fmaxf(s[j][0], s[j][1]));
            cm1 = fmaxf(cm1, fmaxf(s[j][2], s[j][3]));
        }
        cm0 = fmaxf(cm0, __shfl_xor_sync(0xffffffffu, cm0, 1));
        cm0 = fmaxf(cm0, __shfl_xor_sync(0xffffffffu, cm0, 2));
        cm1 = fmaxf(cm1, __shfl_xor_sync(0xffffffffu, cm1, 1));
        cm1 = fmaxf(cm1, __shfl_xor_sync(0xffffffffu, cm1, 2));
        float m0n = fmaxf(m0r, cm0), m1n = fmaxf(m1r, cm1);
        float cor0 = __expf(m0r - m0n), cor1 = __expf(m1r - m1n);
        m0r = m0n; m1r = m1n;
        float rs0 = 0.f, rs1 = 0.f;
#pragma unroll
        for (int j = 0; j < 8; ++j) {
            s[j][0] = __expf(s[j][0] - m0n);
            s[j][1] = __expf(s[j][1] - m0n);
            s[j][2] = __expf(s[j][2] - m1n);
            s[j][3] = __expf(s[j][3] - m1n);
            rs0 += s[j][0] + s[j][1];
            rs1 += s[j][2] + s[j][3];
        }
        rs0 += __shfl_xor_sync(0xffffffffu, rs0, 1);
        rs0 += __shfl_xor_sync(0xffffffffu, rs0, 2);
        rs1 += __shfl_xor_sync(0xffffffffu, rs1, 1);
        rs1 += __shfl_xor_sync(0xffffffffu, rs1, 2);
        l0r = l0r * cor0 + rs0;
        l1r = l1r * cor1 + rs1;
#pragma unroll
        for (int j = 0; j < 8; ++j) {
            o[j][0] *= cor0; o[j][1] *= cor0;
            o[j][2] *= cor1; o[j][3] *= cor1;
        }

        uint32_t ph[8][2], pl[8][2];
#pragma unroll
        for (int j = 0; j < 8; ++j) {
            float2 v0 = {s[j][0], s[j][1]};
            __nv_bfloat162 hh0 = __float22bfloat162_rn(v0);
            ph[j][0] = *reinterpret_cast<uint32_t*>(&hh0);
            float2 lo0 = {s[j][0] - __bfloat162float(hh0.x),
                          s[j][1] - __bfloat162float(hh0.y)};
            __nv_bfloat162 ll0 = __float22bfloat162_rn(lo0);
            pl[j][0] = *reinterpret_cast<uint32_t*>(&ll0);
            float2 v1 = {s[j][2], s[j][3]};
            __nv_bfloat162 hh1 = __float22bfloat162_rn(v1);
            ph[j][1] = *reinterpret_cast<uint32_t*>(&hh1);
            float2 lo1 = {s[j][2] - __bfloat162float(hh1.x),
                          s[j][3] - __bfloat162float(hh1.y)};
            __nv_bfloat162 ll1 = __float22bfloat162_rn(lo1);
            pl[j][1] = *reinterpret_cast<uint32_t*>(&ll1);
        }

#pragma unroll
        for (int kk = 0; kk < 4; ++kk) {
            uint32_t a_h[4] = { ph[2*kk][0], ph[2*kk][1], ph[2*kk+1][0], ph[2*kk+1][1] };
            uint32_t a_l[4] = { pl[2*kk][0], pl[2*kk][1], pl[2*kk+1][0], pl[2*kk+1][1] };
            uint32_t vbh[8][2], vbl[8][2];
            const int srow = kk * 16 + i + ((g >> 1) << 3);
#pragma unroll
            for (int dg = 0; dg < 4; ++dg) {
                int ck = dg * 2 + (g & 1);
                uint32_t off = (uint32_t)(srow * 128 + ((ck ^ (srow & 7)) << 4));
                uint32_t r4[4];
                LDSM4T(r4, stb + 16384 + off);
                vbh[dg * 2][0] = r4[0]; vbh[dg * 2][1] = r4[2];
                vbh[dg * 2 + 1][0] = r4[1]; vbh[dg * 2 + 1][1] = r4[3];
                LDSM4T(r4, stb + 24576 + off);
                vbl[dg * 2][0] = r4[0]; vbl[dg * 2][1] = r4[2];
                vbl[dg * 2 + 1][0] = r4[1]; vbl[dg * 2 + 1][1] = r4[3];
            }
#pragma unroll
            for (int dt = 0; dt < 8; ++dt) {
                MMA16816(o[dt], a_h, vbh[dt]);
                MMA16816(o[dt], a_h, vbl[dt]);
                MMA16816(o[dt], a_l, vbh[dt]);
            }
        }

        __syncthreads();
        if (c + 2 < 16) {
            LOAD_CHUNK(c + 2, c & 1);
            asm volatile("cp.async.commit_group;" ::: "memory");
        }
    }

    float inv0 = 1.f / l0r, inv1 = 1.f / l1r;
    int t_row0 = t0 + w * 16 + rq;
    int t_row1 = t_row0 + 8;
#pragma unroll
    for (int j = 0; j < 8; ++j) {
        int d = j * 8 + cq;
        size_t i0 = ((size_t)t_row0 * Bb + b) * Ee + h * HD + d;
        size_t i1 = ((size_t)t_row1 * Bb + b) * Ee + h * HD + d;
        float x0 = o[j][0] * inv0, y0 = o[j][1] * inv0;
        float x1 = o[j][2] * inv1, y1 = o[j][3] * inv1;
        float2 v0 = {x0, y0};
        __nv_bfloat162 hh0 = __float22bfloat162_rn(v0);
        *reinterpret_cast<__nv_bfloat162*>(g_AOh + i0) = hh0;
        float2 lo0 = {x0 - __bfloat162float(hh0.x), y0 - __bfloat162float(hh0.y)};
        *reinterpret_cast<__nv_bfloat162*>(g_AOl + i0) = __float22bfloat162_rn(lo0);
        float2 v1 = {x1, y1};
        __nv_bfloat162 hh1 = __float22bfloat162_rn(v1);
        *reinterpret_cast<__nv_bfloat162*>(g_AOh + i1) = hh1;
        float2 lo1 = {x1 - __bfloat162float(hh1.x), y1 - __bfloat162float(hh1.y)};
        *reinterpret_cast<__nv_bfloat162*>(g_AOl + i1) = __float22bfloat162_rn(lo1);
    }
#undef LOAD_CHUNK
}

// ---------------------------------------------------------------------------
extern "C" void kernel_launch(void* const* d_in, const int* in_sizes, int n_in,
                              void* d_out, int out_size)
{
    const float* query = (const float*)d_in[0];
    const float* ipw   = (const float*)d_in[1];
    const float* ipb   = (const float*)d_in[2];
    const float* il    = (const float*)d_in[3];
    const float* ir    = (const float*)d_in[4];
    const float* opw   = (const float*)d_in[5];
    const float* opb   = (const float*)d_in[6];
    const float* ol    = (const float*)d_in[7];
    const float* orr   = (const float*)d_in[8];
    const float* rpb   = (const float*)d_in[9];
    float* out = (float*)d_out;

    static bool attr_set = false;
    if (!attr_set) {
        cudaFuncSetAttribute(gemm_mma<0>,
            cudaFuncAttributeMaxDynamicSharedMemorySize, 98304);
        cudaFuncSetAttribute(gemm_mma<1>,
            cudaFuncAttributeMaxDynamicSharedMemorySize, 98304);
        cudaFuncSetAttribute(attn_mma,
            cudaFuncAttributeMaxDynamicSharedMemorySize, 98304);
        attr_set = true;
    }

    weff_kernel<0><<<(F3 * Ee + 255) / 256, 256>>>(ipw, il, ir);
    weff_kernel<1><<<(Ee * Ee + 255) / 256, 256>>>(opw, ol, orr);
    qsplit_kernel<<<Nrows * Ee / 1024, 256>>>(query);

    gemm_mma<0><<<dim3(F3 / BN, Nrows / BM), 256, 98304>>>(ipb, nullptr, F3, Ee);

    attn_mma<<<dim3(Bb * Hh, Tt / 128), 256, 98304>>>(rpb);

    gemm_mma<1><<<dim3(Ee / BN, Nrows / BM), 256, 98304>>>(opb, out, Ee, Ee);
}